// round 14
// baseline (speedup 1.0000x reference)
#include <cuda_runtime.h>
#include <math.h>

constexpr int kN  = 20000;
constexpr int kG  = 8;
constexpr int kE  = 640000;
constexpr int kC  = 64;
constexpr int kNB = 8;
constexpr int kL  = 3;
constexpr int TE  = 128;
constexpr int NTILE = kE / TE;
constexpr int EGRID = 152;
constexpr int kNP = 20064;            // species-sorted padded list
constexpr int NGP = kNP / 8;          // 2508 groups
constexpr int GPB = (NGP + EGRID - 1) / EGRID;  // 17 groups per block

__device__ float g_ef[kE * kNB];
__device__ float g_y1[kE * 3];
__device__ float g_mask[kE];
__device__ int   g_snd[kE];
__device__ int   g_rcv[kE];
__device__ int   g_psnd[kE];
__device__ int   g_prcv[kE];
__device__ int   g_slot[kE];
__device__ int   g_cnt[kN];
__device__ int   g_base[kN];
__device__ int   g_scnt[8];
__device__ int   g_spbase[8];
__device__ int   g_spslot[kN];
__device__ int   g_npsort[kNP];
__device__ int   g_sp[kN];
__device__ int   g_batch[kN];
__device__ float g_s[kN * kC];
__device__ float g_xf[kN * kC];
__device__ float g_xfs[8 * kC];
__device__ float g_sup0[8 * kC];
__device__ float g_v[kN * kC * 3];
__device__ float g_supv[kN * kC * 4];
__device__ float g_agg[kN * kC * 4];
__device__ float g_outs[kL * kN * 9];

typedef unsigned long long ull;

__device__ __forceinline__ float silu_f(float x) {
    return __fdividef(x, 1.0f + __expf(-x));
}
__device__ __forceinline__ ull pack2(float lo, float hi) {
    ull r; asm("mov.b64 %0,{%1,%2};" : "=l"(r) : "f"(lo), "f"(hi)); return r;
}
__device__ __forceinline__ void unpack2(ull v, float& lo, float& hi) {
    asm("mov.b64 {%0,%1},%2;" : "=f"(lo), "=f"(hi) : "l"(v));
}
__device__ __forceinline__ void fma2(ull& d, ull a, ull b) {
    asm("fma.rn.f32x2 %0,%1,%2,%0;" : "+l"(d) : "l"(a), "l"(b));
}
__device__ __forceinline__ void red4(float* p, float a, float b, float c, float d) {
    asm volatile("red.global.add.v4.f32 [%0],{%1,%2,%3,%4};"
                 :: "l"(p), "f"(a), "f"(b), "f"(c), "f"(d) : "memory");
}
__device__ __forceinline__ void cpa16(unsigned int dst, const void* src) {
    asm volatile("cp.async.ca.shared.global [%0], [%1], 16;" :: "r"(dst), "l"(src));
}
__device__ __forceinline__ void cpa_commit() {
    asm volatile("cp.async.commit_group;" ::: "memory");
}
__device__ __forceinline__ void cpa_wait0() {
    asm volatile("cp.async.wait_group 0;" ::: "memory");
}

__global__ void k_conv(const int* eraw, const int* braw, const int* spraw) {
    __shared__ int sf;
    if (threadIdx.x == 0) {
        int f = 1;
        for (int k = 0; k < 64; k++)
            if (spraw[2 * k + 1] != 0) { f = 0; break; }
        sf = f;
    }
    __syncthreads();
    int f = sf;
    int i = blockIdx.x * blockDim.x + threadIdx.x;
    if (i < kN) {
        g_batch[i] = f ? braw[2 * i] : braw[i];
        int sp = f ? spraw[2 * i] : spraw[i];
        g_sp[i] = sp;
        g_spslot[i] = atomicAdd(&g_scnt[sp], 1);
    }
    if (i < kE) {
        int snd = f ? eraw[2 * i]        : eraw[i];
        int rcv = f ? eraw[2 * (kE + i)] : eraw[kE + i];
        g_snd[i] = snd;
        g_rcv[i] = rcv;
        g_slot[i] = atomicAdd(&g_cnt[rcv], 1);
    }
}

__global__ void k_scan(float* __restrict__ out,
                       const float* __restrict__ Wemb,
                       const float* __restrict__ Wx,
                       const float* __restrict__ Wups0) {
    __shared__ int wsum[32];
    __shared__ int carry_s;
    int tid = threadIdx.x;
    if (tid < 72) out[tid] = 0.0f;
    if (tid < 512) {
        int sp = tid >> 6, c = tid & 63;
        float a = 0.0f, b = 0.0f;
#pragma unroll 8
        for (int k = 0; k < kC; k++) {
            float w = Wemb[sp * kC + k];
            a += w * Wx[k * kC + c];
            b += w * Wups0[k * kC + c];
        }
        g_xfs[tid]  = a;
        g_sup0[tid] = b;
    }
    if (tid == 0) {
        int b = 0;
        for (int s = 0; s < 8; s++) {
            int c = g_scnt[s];
            g_scnt[s] = 0;
            g_spbase[s] = b;
            b += ((c + 7) >> 3) << 3;
        }
        carry_s = 0;
    }
    for (int i = tid; i < kNP; i += 1024) g_npsort[i] = -1;
    __syncthreads();

    int lane = tid & 31, wid = tid >> 5;
    for (int base = 0; base < kN; base += 1024) {
        int i = base + tid;
        int v = (i < kN) ? g_cnt[i] : 0;
        if (i < kN) g_cnt[i] = 0;
        int x = v;
#pragma unroll
        for (int off = 1; off < 32; off <<= 1) {
            int t = __shfl_up_sync(0xffffffffu, x, off);
            if (lane >= off) x += t;
        }
        if (lane == 31) wsum[wid] = x;
        __syncthreads();
        if (wid == 0) {
            int y = wsum[lane];
#pragma unroll
            for (int off = 1; off < 32; off <<= 1) {
                int t = __shfl_up_sync(0xffffffffu, y, off);
                if (lane >= off) y += t;
            }
            wsum[lane] = y;
        }
        __syncthreads();
        int excl = x - v + (wid ? wsum[wid - 1] : 0);
        if (i < kN) g_base[i] = carry_s + excl;
        int total = wsum[31];
        __syncthreads();
        if (tid == 0) carry_s += total;
        __syncthreads();
    }
}

__global__ void k_geominit(const float* __restrict__ pos,
                           const float* __restrict__ cell,
                           const float* __restrict__ Sij,
                           const float* __restrict__ Wemb) {
    int t = blockIdx.x * blockDim.x + threadIdx.x;
    if (t < kE) {
        int e = t;
        int snd = g_snd[e], rcv = g_rcv[e];
        int p = g_base[rcv] + g_slot[e];
        g_psnd[p] = snd;
        g_prcv[p] = rcv;
        int b = g_batch[snd];
        float s0 = Sij[e * 3 + 0], s1 = Sij[e * 3 + 1], s2 = Sij[e * 3 + 2];
        const float* cb = cell + b * 9;
        float sh0 = s0 * cb[0] + s1 * cb[3] + s2 * cb[6];
        float sh1 = s0 * cb[1] + s1 * cb[4] + s2 * cb[7];
        float sh2 = s0 * cb[2] + s1 * cb[5] + s2 * cb[8];
        const float invcut = 1.0f / 6.0f;
        float r0 = (pos[rcv * 3 + 0] - pos[snd * 3 + 0] + sh0) * invcut;
        float r1 = (pos[rcv * 3 + 1] - pos[snd * 3 + 1] + sh1) * invcut;
        float r2 = (pos[rcv * 3 + 2] - pos[snd * 3 + 2] + sh2) * invcut;
        float len = sqrtf(r0 * r0 + r1 * r1 + r2 * r2);
        float mask = (len > 0.0f) ? 1.0f : 0.0f;
        float safe = (len > 0.0f) ? len : 1.0f;
        float inv = 1.0f / safe;
        const float sq3 = 1.7320508075688772f;
        g_y1[p * 3 + 0] = sq3 * r0 * inv;
        g_y1[p * 3 + 1] = sq3 * r1 * inv;
        g_y1[p * 3 + 2] = sq3 * r2 * inv;
        float x = safe;
        float env = (x < 1.0f) ? (1.0f - 6.0f * x * x + 8.0f * x * x * x - 3.0f * x * x * x * x) : 0.0f;
        float fac = 1.4142135623730951f * inv * env * mask;
        const float pi = 3.14159265358979323846f;
#pragma unroll
        for (int nb = 1; nb <= kNB; nb++)
            g_ef[p * kNB + nb - 1] = fac * sinf(pi * (float)nb * safe);
        g_mask[p] = mask;
    }
    if (t < kN) {
        g_npsort[g_spbase[g_sp[t]] + g_spslot[t]] = t;
    }
    if (t < kN * kC) {
        int n = t / kC, c = t % kC;
        int sp = g_sp[n];
        g_s[t]  = Wemb[sp * kC + c];
        g_xf[t] = g_xfs[sp * kC + c];
        g_v[n * 192 + c * 3 + 0] = 0.0f;
        g_v[n * 192 + c * 3 + 1] = 0.0f;
        g_v[n * 192 + c * 3 + 2] = 0.0f;
        *(float4*)&g_agg[t * 4] = make_float4(0.f, 0.f, 0.f, 0.f);
        *(float4*)&g_supv[t * 4] = make_float4(g_sup0[sp * kC + c], 0.f, 0.f, 0.f);
    }
}

constexpr int PF_STRIDE = 1792;
constexpr int EDGE_SMEM = (512 + 64 + 64 + 4096 + 16384 + 16384 + 16384 + 2 * PF_STRIDE) * 4;

template <bool FULL>
__global__ __launch_bounds__(512, 1) void k_edge(const float* __restrict__ Wr1,
                                                 const float* __restrict__ br1,
                                                 const float* __restrict__ Wr2,
                                                 const float* __restrict__ br2,
                                                 const float* __restrict__ Wr3) {
    extern __shared__ float sm[];
    float* sWr1 = sm;
    float* sbr1 = sWr1 + 512;
    float* sbr2 = sbr1 + 64;
    float* sWr2 = sbr2 + 64;
    float* sWr3 = sWr2 + 4096;
    ull*   sh1d = (ull*)(sWr3 + 16384);
    ull*   sh2d = sh1d + TE * 64;
    float* pf   = (float*)(sh2d + TE * 64);

    int tid = threadIdx.x;
    for (int i = tid; i < 128; i += 512) ((float4*)sWr1)[i] = ((const float4*)Wr1)[i];
    if (tid < 64) { sbr1[tid] = br1[tid]; sbr2[tid] = br2[tid]; }
    for (int i = tid; i < 1024; i += 512) ((float4*)sWr2)[i] = ((const float4*)Wr2)[i];
    for (int i = tid; i < 4096; i += 512) ((float4*)sWr3)[i] = ((const float4*)Wr3)[i];

    int eg = tid >> 4;
    int cq = tid & 15;
    int c0 = cq * 4;
    int eb = eg * 4;

    const float inv_sqrt3 = 0.5773502691896258f;
    constexpr int NT = FULL ? 4 : 2;

    unsigned int pf_s0 = (unsigned int)__cvta_generic_to_shared(pf);
    auto prefetch = [&](int tile, int buf) {
        if (tid < 448) {
            unsigned int dst = pf_s0 + (buf * PF_STRIDE) * 4;
            if (tid < 256) {
                cpa16(dst + tid * 16, g_ef + tile * (TE * 8) + tid * 4);
            } else if (tid < 352) {
                int j = tid - 256;
                cpa16(dst + 1024 * 4 + j * 16, g_y1 + tile * (TE * 3) + j * 4);
            } else if (tid < 384) {
                int j = tid - 352;
                cpa16(dst + 1408 * 4 + j * 16, g_mask + tile * TE + j * 4);
            } else if (tid < 416) {
                int j = tid - 384;
                cpa16(dst + 1536 * 4 + j * 16, g_psnd + tile * TE + j * 4);
            } else {
                int j = tid - 416;
                cpa16(dst + 1664 * 4 + j * 16, g_prcv + tile * TE + j * 4);
            }
        }
        cpa_commit();
    };

    int pb = 0;
    prefetch(blockIdx.x, 0);

    for (int tile = blockIdx.x; tile < NTILE; tile += EGRID) {
        cpa_wait0();
        __syncthreads();
        float* pef = pf + pb * PF_STRIDE;
        float* py  = pef + 1024;
        float* pmk = pef + 1408;
        int*  psnd = (int*)(pef + 1536);
        int*  prcv = (int*)(pef + 1664);

        int nt = tile + EGRID;
        if (nt < NTILE) prefetch(nt, pb ^ 1);

        {
            ull acc[4][2];
            ull b0 = pack2(sbr1[c0], sbr1[c0 + 1]);
            ull b1 = pack2(sbr1[c0 + 2], sbr1[c0 + 3]);
#pragma unroll
            for (int i = 0; i < 4; i++) { acc[i][0] = b0; acc[i][1] = b1; }
#pragma unroll
            for (int k = 0; k < 8; k++) {
                ulonglong2 w = *(const ulonglong2*)&sWr1[k * 64 + c0];
#pragma unroll
                for (int i = 0; i < 4; i++) {
                    float h = pef[(eb + i) * 8 + k];
                    ull ha = pack2(h, h);
                    fma2(acc[i][0], ha, w.x);
                    fma2(acc[i][1], ha, w.y);
                }
            }
#pragma unroll
            for (int i = 0; i < 4; i++) {
                float l0, h0, l1, h1v;
                unpack2(acc[i][0], l0, h0);
                unpack2(acc[i][1], l1, h1v);
                float a0 = silu_f(l0), a1 = silu_f(h0);
                float a2 = silu_f(l1), a3 = silu_f(h1v);
                ulonglong2 st0, st1;
                st0.x = pack2(a0, a0); st0.y = pack2(a1, a1);
                st1.x = pack2(a2, a2); st1.y = pack2(a3, a3);
                *(ulonglong2*)&sh1d[(eb + i) * 64 + c0]     = st0;
                *(ulonglong2*)&sh1d[(eb + i) * 64 + c0 + 2] = st1;
            }
        }
        __syncthreads();

        {
            ull acc[4][2];
            ull b0 = pack2(sbr2[c0], sbr2[c0 + 1]);
            ull b1 = pack2(sbr2[c0 + 2], sbr2[c0 + 3]);
#pragma unroll
            for (int i = 0; i < 4; i++) { acc[i][0] = b0; acc[i][1] = b1; }
#pragma unroll 2
            for (int k = 0; k < 64; k += 2) {
                ulonglong2 w0 = *(const ulonglong2*)&sWr2[k * 64 + c0];
                ulonglong2 w1 = *(const ulonglong2*)&sWr2[(k + 1) * 64 + c0];
#pragma unroll
                for (int i = 0; i < 4; i++) {
                    ulonglong2 hp = *(const ulonglong2*)&sh1d[(eb + i) * 64 + k];
                    fma2(acc[i][0], hp.x, w0.x);
                    fma2(acc[i][1], hp.x, w0.y);
                    fma2(acc[i][0], hp.y, w1.x);
                    fma2(acc[i][1], hp.y, w1.y);
                }
            }
#pragma unroll
            for (int i = 0; i < 4; i++) {
                float l0, h0, l1, h1v;
                unpack2(acc[i][0], l0, h0);
                unpack2(acc[i][1], l1, h1v);
                float a0 = silu_f(l0), a1 = silu_f(h0);
                float a2 = silu_f(l1), a3 = silu_f(h1v);
                ulonglong2 st0, st1;
                st0.x = pack2(a0, a0); st0.y = pack2(a1, a1);
                st1.x = pack2(a2, a2); st1.y = pack2(a3, a3);
                *(ulonglong2*)&sh2d[(eb + i) * 64 + c0]     = st0;
                *(ulonglong2*)&sh2d[(eb + i) * 64 + c0 + 2] = st1;
            }
        }
        __syncthreads();

        ull acc3[4][NT][2];
#pragma unroll
        for (int i = 0; i < 4; i++)
#pragma unroll
            for (int t = 0; t < NT; t++) { acc3[i][t][0] = 0ULL; acc3[i][t][1] = 0ULL; }

#pragma unroll 2
        for (int k = 0; k < 64; k += 2) {
            ulonglong2 hp[4];
#pragma unroll
            for (int i = 0; i < 4; i++)
                hp[i] = *(const ulonglong2*)&sh2d[(eb + i) * 64 + k];
            const float* wr0 = &sWr3[k * 256 + c0];
            const float* wr1 = wr0 + 256;
#pragma unroll
            for (int tt = 0; tt < NT; tt++) {
                int t = FULL ? tt : tt * 2;
                ulonglong2 wa = *(const ulonglong2*)(wr0 + t * 64);
                ulonglong2 wb = *(const ulonglong2*)(wr1 + t * 64);
#pragma unroll
                for (int i = 0; i < 4; i++) {
                    fma2(acc3[i][tt][0], hp[i].x, wa.x);
                    fma2(acc3[i][tt][1], hp[i].x, wa.y);
                    fma2(acc3[i][tt][0], hp[i].y, wb.x);
                    fma2(acc3[i][tt][1], hp[i].y, wb.y);
                }
            }
        }

        {
            int cur = -1;
            float aq[4][4];
#pragma unroll
            for (int i = 0; i < 4; i++) {
                int le = eb + i;
                int rcv = prcv[le];
                if (rcv != cur) {
                    if (cur >= 0) {
                        float* agp = &g_agg[cur * 256];
#pragma unroll
                        for (int q = 0; q < 4; q++)
                            red4(agp + (c0 + q) * 4, aq[q][0], aq[q][1], aq[q][2], aq[q][3]);
                    }
                    cur = rcv;
#pragma unroll
                    for (int q = 0; q < 4; q++)
                        aq[q][0] = aq[q][1] = aq[q][2] = aq[q][3] = 0.0f;
                }
                float msk = pmk[le] * 0.03125f;
                float y0 = py[le * 3 + 0], y1v = py[le * 3 + 1], y2 = py[le * 3 + 2];
                const float4* svp = (const float4*)&g_supv[psnd[le] * 256];
                if (FULL) {
#pragma unroll
                    for (int p = 0; p < 2; p++) {
                        float wt[4][2];
#pragma unroll
                        for (int t = 0; t < NT; t++) unpack2(acc3[i][t][p], wt[t][0], wt[t][1]);
#pragma unroll
                        for (int jj = 0; jj < 2; jj++) {
                            int q = 2 * p + jj;
                            float w0 = wt[0][jj] * msk, w1 = wt[1][jj] * msk;
                            float w2 = wt[2][jj] * msk, w3 = wt[3][jj] * msk;
                            float4 s4 = svp[c0 + q];
                            float dot = (s4.y * y0 + s4.z * y1v + s4.w * y2) * inv_sqrt3;
                            float a0 = w2 * s4.x;
                            aq[q][0] += w0 * s4.x + w1 * dot;
                            aq[q][1] += a0 * y0  + w3 * s4.y;
                            aq[q][2] += a0 * y1v + w3 * s4.z;
                            aq[q][3] += a0 * y2  + w3 * s4.w;
                        }
                    }
                } else {
#pragma unroll
                    for (int p = 0; p < 2; p++) {
                        float wt0[2], wt2[2];
                        unpack2(acc3[i][0][p], wt0[0], wt0[1]);
                        unpack2(acc3[i][1][p], wt2[0], wt2[1]);
#pragma unroll
                        for (int jj = 0; jj < 2; jj++) {
                            int q = 2 * p + jj;
                            float w0 = wt0[jj] * msk;
                            float w2 = wt2[jj] * msk;
                            float4 s4 = svp[c0 + q];
                            float a0 = w2 * s4.x;
                            aq[q][0] += w0 * s4.x;
                            aq[q][1] += a0 * y0;
                            aq[q][2] += a0 * y1v;
                            aq[q][3] += a0 * y2;
                        }
                    }
                }
            }
            if (cur >= 0) {
                float* agp = &g_agg[cur * 256];
#pragma unroll
                for (int q = 0; q < 4; q++)
                    red4(agp + (c0 + q) * 4, aq[q][0], aq[q][1], aq[q][2], aq[q][3]);
            }
        }
        pb ^= 1;
    }
}

constexpr int NODE_SMEM = 32768 * 4;

__global__ __launch_bounds__(512, 1) void k_node(const float* __restrict__ Wms,
                                                 const float* __restrict__ Wmv,
                                                 const float* __restrict__ Wscs,
                                                 const float* __restrict__ Wscv,
                                                 const float* __restrict__ Wps,
                                                 const float* __restrict__ Wpv,
                                                 const float* __restrict__ Wread,
                                                 const float* __restrict__ WupS,
                                                 const float* __restrict__ WupV,
                                                 int l, int do_up) {
    extern __shared__ float sm[];
    float* sWms = sm;
    float* sWmv = sWms + 4096;
    float* sWps = sWmv + 4096;
    float* sWpv = sWps + 4096;
    float* sWus = sWpv + 4096;
    float* sWuv = sWus + 4096;
    float* sagg = sWuv + 4096;
    float* sold = sagg + 2048;
    float* vold = sold + 512;
    float* sts  = vold + 1536;
    float* stv  = sts + 512;
    float* snew = stv + 1536;
    float* vnew = snew + 512;
    __shared__ int s_sp;

    int tid = threadIdx.x;
    for (int i = tid; i < 1024; i += 512) {
        ((float4*)sWms)[i] = ((const float4*)Wms)[i];
        ((float4*)sWmv)[i] = ((const float4*)Wmv)[i];
        ((float4*)sWps)[i] = ((const float4*)Wps)[i];
        ((float4*)sWpv)[i] = ((const float4*)Wpv)[i];
    }
    if (do_up) {
        for (int i = tid; i < 1024; i += 512) {
            ((float4*)sWus)[i] = ((const float4*)WupS)[i];
            ((float4*)sWuv)[i] = ((const float4*)WupV)[i];
        }
    }
    int slot = tid >> 6, o = tid & 63;

    int g0 = blockIdx.x * GPB;
    int g1 = g0 + GPB; if (g1 > NGP) g1 = NGP;

    for (int grp = g0; grp < g1; grp++) {
        int n = g_npsort[grp * 8 + slot];
        bool ok = (n >= 0);
        int nn = ok ? n : 0;
        __syncthreads();
        if (tid == 0) {
            int nref = g_npsort[grp * 8];
            s_sp = (nref >= 0) ? g_sp[nref] : 0;
        }
        if (ok) {
            *(float4*)&sagg[slot * 256 + o * 4] = *(const float4*)&g_agg[nn * 256 + o * 4];
            *(float4*)&g_agg[nn * 256 + o * 4] = make_float4(0.f, 0.f, 0.f, 0.f);
        } else {
            *(float4*)&sagg[slot * 256 + o * 4] = make_float4(0.f, 0.f, 0.f, 0.f);
        }
        sold[slot * 64 + o] = g_s[nn * 64 + o];
        vold[slot * 192 + o * 3 + 0] = g_v[nn * 192 + o * 3 + 0];
        vold[slot * 192 + o * 3 + 1] = g_v[nn * 192 + o * 3 + 1];
        vold[slot * 192 + o * 3 + 2] = g_v[nn * 192 + o * 3 + 2];
        __syncthreads();

        int sp = s_sp;
        const float* Wss = Wscs + sp * 4096;
        const float* Wsv = Wscv + sp * 4096;

        float ms = 0, mv0 = 0, mv1 = 0, mv2 = 0;
        float scs = 0, scv0 = 0, scv1 = 0, scv2 = 0;
#pragma unroll 4
        for (int c = 0; c < 64; c++) {
            const float* ag = &sagg[slot * 256 + c * 4];
            ms  += ag[0] * sWms[c * 64 + o];
            float wm = sWmv[c * 64 + o];
            mv0 += ag[1] * wm; mv1 += ag[2] * wm; mv2 += ag[3] * wm;
            scs += sold[slot * 64 + c] * Wss[c * 64 + o];
            float wv = Wsv[c * 64 + o];
            scv0 += vold[slot * 192 + c * 3 + 0] * wv;
            scv1 += vold[slot * 192 + c * 3 + 1] * wv;
            scv2 += vold[slot * 192 + c * 3 + 2] * wv;
        }
        float xfo = g_xf[nn * 64 + o];
        sts[slot * 64 + o] = xfo * ms;
        stv[slot * 192 + o * 3 + 0] = xfo * mv0;
        stv[slot * 192 + o * 3 + 1] = xfo * mv1;
        stv[slot * 192 + o * 3 + 2] = xfo * mv2;
        __syncthreads();

        float sn = scs, vn0 = scv0, vn1 = scv1, vn2 = scv2;
#pragma unroll 4
        for (int c = 0; c < 64; c++) {
            sn += sts[slot * 64 + c] * sWps[c * 64 + o];
            float wp = sWpv[c * 64 + o];
            vn0 += stv[slot * 192 + c * 3 + 0] * wp;
            vn1 += stv[slot * 192 + c * 3 + 1] * wp;
            vn2 += stv[slot * 192 + c * 3 + 2] * wp;
        }
        if (ok) {
            g_s[nn * 64 + o] = sn;
            g_v[nn * 192 + o * 3 + 0] = vn0;
            g_v[nn * 192 + o * 3 + 1] = vn1;
            g_v[nn * 192 + o * 3 + 2] = vn2;
        }
        snew[slot * 64 + o] = sn;
        vnew[slot * 192 + o * 3 + 0] = vn0;
        vnew[slot * 192 + o * 3 + 1] = vn1;
        vnew[slot * 192 + o * 3 + 2] = vn2;
        __syncthreads();

        if (o < 9 && ok) {
            int ro = o / 3, m = o % 3;
            float a = 0.0f;
#pragma unroll 8
            for (int c = 0; c < 64; c++) a += vnew[slot * 192 + c * 3 + m] * Wread[ro * 64 + c];
            g_outs[l * kN * 9 + nn * 9 + o] = a;
        }

        if (do_up && ok) {
            float su = 0.0f, u0 = 0.0f, u1 = 0.0f, u2 = 0.0f;
#pragma unroll 4
            for (int c = 0; c < 64; c++) {
                su += snew[slot * 64 + c] * sWus[c * 64 + o];
                float w = sWuv[c * 64 + o];
                u0 += vnew[slot * 192 + c * 3 + 0] * w;
                u1 += vnew[slot * 192 + c * 3 + 1] * w;
                u2 += vnew[slot * 192 + c * 3 + 2] * w;
            }
            *(float4*)&g_supv[nn * 256 + o * 4] = make_float4(su, u0, u1, u2);
        }
    }
}

__global__ void k_final(float* __restrict__ out) {
    __shared__ float acc[72];
    int tid = threadIdx.x;
    if (tid < 72) acc[tid] = 0.0f;
    __syncthreads();
    int n = blockIdx.x * blockDim.x + tid;
    if (n < kN) {
        int b = g_batch[n];
#pragma unroll
        for (int j = 0; j < 9; j++) {
            float x = 0.0f;
#pragma unroll
            for (int l = 0; l < kL; l++) x += silu_f(g_outs[l * kN * 9 + n * 9 + j]);
            atomicAdd(&acc[b * 9 + j], x);
        }
    }
    __syncthreads();
    if (tid < 72) atomicAdd(&out[tid], acc[tid]);
}

extern "C" void kernel_launch(void* const* d_in, const int* in_sizes, int n_in,
                              void* d_out, int out_size) {
    const float* pos  = (const float*)d_in[0];
    const float* cell = (const float*)d_in[1];
    const float* Sij  = (const float*)d_in[2];
    const float* Wemb = (const float*)d_in[3];
    const float* Wx   = (const float*)d_in[4];
    const float* Wups = (const float*)d_in[5];
    const float* Wupv = (const float*)d_in[6];
    const float* Wr1  = (const float*)d_in[7];
    const float* br1  = (const float*)d_in[8];
    const float* Wr2  = (const float*)d_in[9];
    const float* br2  = (const float*)d_in[10];
    const float* Wr3  = (const float*)d_in[11];
    const float* Wms  = (const float*)d_in[12];
    const float* Wmv  = (const float*)d_in[13];
    const float* Wscs = (const float*)d_in[14];
    const float* Wscv = (const float*)d_in[15];
    const float* Wps  = (const float*)d_in[16];
    const float* Wpv  = (const float*)d_in[17];
    const float* Wread= (const float*)d_in[18];
    const int* ei     = (const int*)d_in[19];
    const int* braw   = (const int*)d_in[20];
    const int* spraw  = (const int*)d_in[21];
    float* out = (float*)d_out;

    cudaFuncSetAttribute(k_edge<true>,  cudaFuncAttributeMaxDynamicSharedMemorySize, EDGE_SMEM);
    cudaFuncSetAttribute(k_edge<false>, cudaFuncAttributeMaxDynamicSharedMemorySize, EDGE_SMEM);
    cudaFuncSetAttribute(k_node, cudaFuncAttributeMaxDynamicSharedMemorySize, NODE_SMEM);

    k_conv<<<(kE + 255) / 256, 256>>>(ei, braw, spraw);
    k_scan<<<1, 1024>>>(out, Wemb, Wx, Wups);
    k_geominit<<<(kN * kC + 255) / 256, 256>>>(pos, cell, Sij, Wemb);

    for (int l = 0; l < kL; l++) {
        if (l == 0)
            k_edge<false><<<EGRID, 512, EDGE_SMEM>>>(Wr1 + l * 512, br1 + l * 64,
                                                     Wr2 + l * 4096, br2 + l * 64,
                                                     Wr3 + l * 16384);
        else
            k_edge<true><<<EGRID, 512, EDGE_SMEM>>>(Wr1 + l * 512, br1 + l * 64,
                                                    Wr2 + l * 4096, br2 + l * 64,
                                                    Wr3 + l * 16384);
        int do_up = (l < kL - 1) ? 1 : 0;
        k_node<<<EGRID, 512, NODE_SMEM>>>(Wms + l * 4096, Wmv + l * 4096,
                                          Wscs + l * 32768, Wscv + l * 32768,
                                          Wps + l * 4096, Wpv + l * 4096,
                                          Wread + l * 192,
                                          Wups + (l + 1) * 4096, Wupv + (l + 1) * 4096,
                                          l, do_up);
    }
    k_final<<<(kN + 255) / 256, 256>>>(out);
}

// round 15
// speedup vs baseline: 1.0467x; 1.0467x over previous
#include <cuda_runtime.h>
#include <math.h>

constexpr int kN  = 20000;
constexpr int kG  = 8;
constexpr int kE  = 640000;
constexpr int kC  = 64;
constexpr int kNB = 8;
constexpr int kL  = 3;
constexpr int TE  = 128;
constexpr int NTILE = kE / TE;
constexpr int EGRID = 152;
constexpr int NGROUP = kN / 8;

__device__ float g_ef[kE * kNB];
__device__ float g_y1[kE * 3];
__device__ float g_mask[kE];
__device__ int   g_snd[kE];
__device__ int   g_rcv[kE];
__device__ int   g_psnd[kE];
__device__ int   g_prcv[kE];
__device__ int   g_pssp[kE];          // species of sender, sorted edge order
__device__ int   g_slot[kE];
__device__ int   g_cnt[kN];
__device__ int   g_base[kN];
__device__ int   g_sp[kN];
__device__ int   g_batch[kN];
__device__ float g_s[kN * kC];
__device__ float g_xf[kN * kC];
__device__ float g_xfs[8 * kC];
__device__ float g_sup0[8 * kC];
__device__ float g_v[kN * kC * 3];
__device__ float g_supv[kN * kC * 4];
__device__ float g_agg[kN * kC * 4];
__device__ float g_outs[kL * kN * 9];

typedef unsigned long long ull;

__device__ __forceinline__ float silu_f(float x) {
    return __fdividef(x, 1.0f + __expf(-x));
}
__device__ __forceinline__ ull pack2(float lo, float hi) {
    ull r; asm("mov.b64 %0,{%1,%2};" : "=l"(r) : "f"(lo), "f"(hi)); return r;
}
__device__ __forceinline__ void unpack2(ull v, float& lo, float& hi) {
    asm("mov.b64 {%0,%1},%2;" : "=f"(lo), "=f"(hi) : "l"(v));
}
__device__ __forceinline__ void fma2(ull& d, ull a, ull b) {
    asm("fma.rn.f32x2 %0,%1,%2,%0;" : "+l"(d) : "l"(a), "l"(b));
}
__device__ __forceinline__ void red4(float* p, float a, float b, float c, float d) {
    asm volatile("red.global.add.v4.f32 [%0],{%1,%2,%3,%4};"
                 :: "l"(p), "f"(a), "f"(b), "f"(c), "f"(d) : "memory");
}
__device__ __forceinline__ void cpa16(unsigned int dst, const void* src) {
    asm volatile("cp.async.ca.shared.global [%0], [%1], 16;" :: "r"(dst), "l"(src));
}
__device__ __forceinline__ void cpa_commit() {
    asm volatile("cp.async.commit_group;" ::: "memory");
}
__device__ __forceinline__ void cpa_wait0() {
    asm volatile("cp.async.wait_group 0;" ::: "memory");
}

__global__ void k_conv(const int* eraw, const int* braw, const int* spraw) {
    __shared__ int sf;
    if (threadIdx.x == 0) {
        int f = 1;
        for (int k = 0; k < 64; k++)
            if (spraw[2 * k + 1] != 0) { f = 0; break; }
        sf = f;
    }
    __syncthreads();
    int f = sf;
    int i = blockIdx.x * blockDim.x + threadIdx.x;
    if (i < kN) {
        g_batch[i] = f ? braw[2 * i] : braw[i];
        g_sp[i]    = f ? spraw[2 * i] : spraw[i];
    }
    if (i < kE) {
        int snd = f ? eraw[2 * i]        : eraw[i];
        int rcv = f ? eraw[2 * (kE + i)] : eraw[kE + i];
        g_snd[i] = snd;
        g_rcv[i] = rcv;
        g_slot[i] = atomicAdd(&g_cnt[rcv], 1);
    }
}

__global__ void k_scan(float* __restrict__ out,
                       const float* __restrict__ Wemb,
                       const float* __restrict__ Wx,
                       const float* __restrict__ Wups0) {
    __shared__ int wsum[32];
    __shared__ int carry_s;
    int tid = threadIdx.x;
    if (tid < 72) out[tid] = 0.0f;
    if (tid < 512) {
        int sp = tid >> 6, c = tid & 63;
        float a = 0.0f, b = 0.0f;
#pragma unroll 8
        for (int k = 0; k < kC; k++) {
            float w = Wemb[sp * kC + k];
            a += w * Wx[k * kC + c];
            b += w * Wups0[k * kC + c];
        }
        g_xfs[tid]  = a;
        g_sup0[tid] = b;
    }
    if (tid == 0) carry_s = 0;
    __syncthreads();

    int lane = tid & 31, wid = tid >> 5;
    for (int base = 0; base < kN; base += 1024) {
        int i = base + tid;
        int v = (i < kN) ? g_cnt[i] : 0;
        if (i < kN) g_cnt[i] = 0;
        int x = v;
#pragma unroll
        for (int off = 1; off < 32; off <<= 1) {
            int t = __shfl_up_sync(0xffffffffu, x, off);
            if (lane >= off) x += t;
        }
        if (lane == 31) wsum[wid] = x;
        __syncthreads();
        if (wid == 0) {
            int y = wsum[lane];
#pragma unroll
            for (int off = 1; off < 32; off <<= 1) {
                int t = __shfl_up_sync(0xffffffffu, y, off);
                if (lane >= off) y += t;
            }
            wsum[lane] = y;
        }
        __syncthreads();
        int excl = x - v + (wid ? wsum[wid - 1] : 0);
        if (i < kN) g_base[i] = carry_s + excl;
        int total = wsum[31];
        __syncthreads();
        if (tid == 0) carry_s += total;
        __syncthreads();
    }
}

__global__ void k_geominit(const float* __restrict__ pos,
                           const float* __restrict__ cell,
                           const float* __restrict__ Sij,
                           const float* __restrict__ Wemb) {
    int t = blockIdx.x * blockDim.x + threadIdx.x;
    if (t < kE) {
        int e = t;
        int snd = g_snd[e], rcv = g_rcv[e];
        int p = g_base[rcv] + g_slot[e];
        g_psnd[p] = snd;
        g_prcv[p] = rcv;
        g_pssp[p] = g_sp[snd];
        int b = g_batch[snd];
        float s0 = Sij[e * 3 + 0], s1 = Sij[e * 3 + 1], s2 = Sij[e * 3 + 2];
        const float* cb = cell + b * 9;
        float sh0 = s0 * cb[0] + s1 * cb[3] + s2 * cb[6];
        float sh1 = s0 * cb[1] + s1 * cb[4] + s2 * cb[7];
        float sh2 = s0 * cb[2] + s1 * cb[5] + s2 * cb[8];
        const float invcut = 1.0f / 6.0f;
        float r0 = (pos[rcv * 3 + 0] - pos[snd * 3 + 0] + sh0) * invcut;
        float r1 = (pos[rcv * 3 + 1] - pos[snd * 3 + 1] + sh1) * invcut;
        float r2 = (pos[rcv * 3 + 2] - pos[snd * 3 + 2] + sh2) * invcut;
        float len = sqrtf(r0 * r0 + r1 * r1 + r2 * r2);
        float mask = (len > 0.0f) ? 1.0f : 0.0f;
        float safe = (len > 0.0f) ? len : 1.0f;
        float inv = 1.0f / safe;
        const float sq3 = 1.7320508075688772f;
        g_y1[p * 3 + 0] = sq3 * r0 * inv;
        g_y1[p * 3 + 1] = sq3 * r1 * inv;
        g_y1[p * 3 + 2] = sq3 * r2 * inv;
        float x = safe;
        float env = (x < 1.0f) ? (1.0f - 6.0f * x * x + 8.0f * x * x * x - 3.0f * x * x * x * x) : 0.0f;
        float fac = 1.4142135623730951f * inv * env * mask;
        const float pi = 3.14159265358979323846f;
#pragma unroll
        for (int nb = 1; nb <= kNB; nb++)
            g_ef[p * kNB + nb - 1] = fac * sinf(pi * (float)nb * safe);
        g_mask[p] = mask;
    }
    if (t < kN * kC) {
        int n = t / kC, c = t % kC;
        int sp = g_sp[n];
        g_s[t]  = Wemb[sp * kC + c];
        g_xf[t] = g_xfs[sp * kC + c];
        g_v[n * 192 + c * 3 + 0] = 0.0f;
        g_v[n * 192 + c * 3 + 1] = 0.0f;
        g_v[n * 192 + c * 3 + 2] = 0.0f;
        *(float4*)&g_agg[t * 4] = make_float4(0.f, 0.f, 0.f, 0.f);
        *(float4*)&g_supv[t * 4] = make_float4(g_sup0[sp * kC + c], 0.f, 0.f, 0.f);
    }
}

constexpr int PF_STRIDE = 1792;
constexpr int EDGE_SMEM = (512 + 64 + 64 + 4096 + 16384 + 16384 + 16384 +
                           2 * PF_STRIDE + 512) * 4;

template <bool FULL>
__global__ __launch_bounds__(512, 1) void k_edge(const float* __restrict__ Wr1,
                                                 const float* __restrict__ br1,
                                                 const float* __restrict__ Wr2,
                                                 const float* __restrict__ br2,
                                                 const float* __restrict__ Wr3) {
    extern __shared__ float sm[];
    float* sWr1 = sm;
    float* sbr1 = sWr1 + 512;
    float* sbr2 = sbr1 + 64;
    float* sWr2 = sbr2 + 64;
    float* sWr3 = sWr2 + 4096;
    ull*   sh1d = (ull*)(sWr3 + 16384);
    ull*   sh2d = sh1d + TE * 64;
    float* pf   = (float*)(sh2d + TE * 64);
    float* ssup0 = pf + 2 * PF_STRIDE;   // 512 floats (layer-0 species table)

    int tid = threadIdx.x;
    for (int i = tid; i < 128; i += 512) ((float4*)sWr1)[i] = ((const float4*)Wr1)[i];
    if (tid < 64) { sbr1[tid] = br1[tid]; sbr2[tid] = br2[tid]; }
    for (int i = tid; i < 1024; i += 512) ((float4*)sWr2)[i] = ((const float4*)Wr2)[i];
    for (int i = tid; i < 4096; i += 512) ((float4*)sWr3)[i] = ((const float4*)Wr3)[i];
    if (!FULL && tid < 512) ssup0[tid] = g_sup0[tid];

    int eg = tid >> 4;
    int cq = tid & 15;
    int c0 = cq * 4;
    int eb = eg * 4;

    const float inv_sqrt3 = 0.5773502691896258f;
    constexpr int NT = FULL ? 4 : 2;

    unsigned int pf_s0 = (unsigned int)__cvta_generic_to_shared(pf);
    auto prefetch = [&](int tile, int buf) {
        if (tid < 448) {
            unsigned int dst = pf_s0 + (buf * PF_STRIDE) * 4;
            if (tid < 256) {
                cpa16(dst + tid * 16, g_ef + tile * (TE * 8) + tid * 4);
            } else if (tid < 352) {
                int j = tid - 256;
                cpa16(dst + 1024 * 4 + j * 16, g_y1 + tile * (TE * 3) + j * 4);
            } else if (tid < 384) {
                int j = tid - 352;
                cpa16(dst + 1408 * 4 + j * 16, g_mask + tile * TE + j * 4);
            } else if (tid < 416) {
                int j = tid - 384;
                const int* src = FULL ? g_psnd : g_pssp;
                cpa16(dst + 1536 * 4 + j * 16, src + tile * TE + j * 4);
            } else {
                int j = tid - 416;
                cpa16(dst + 1664 * 4 + j * 16, g_prcv + tile * TE + j * 4);
            }
        }
        cpa_commit();
    };

    int pb = 0;
    prefetch(blockIdx.x, 0);

    for (int tile = blockIdx.x; tile < NTILE; tile += EGRID) {
        cpa_wait0();
        __syncthreads();
        float* pef = pf + pb * PF_STRIDE;
        float* py  = pef + 1024;
        float* pmk = pef + 1408;
        int*  psnd = (int*)(pef + 1536);   // FULL: sender node; !FULL: sender species
        int*  prcv = (int*)(pef + 1664);

        int nt = tile + EGRID;
        if (nt < NTILE) prefetch(nt, pb ^ 1);

        {
            ull acc[4][2];
            ull b0 = pack2(sbr1[c0], sbr1[c0 + 1]);
            ull b1 = pack2(sbr1[c0 + 2], sbr1[c0 + 3]);
#pragma unroll
            for (int i = 0; i < 4; i++) { acc[i][0] = b0; acc[i][1] = b1; }
#pragma unroll
            for (int k = 0; k < 8; k++) {
                ulonglong2 w = *(const ulonglong2*)&sWr1[k * 64 + c0];
#pragma unroll
                for (int i = 0; i < 4; i++) {
                    float h = pef[(eb + i) * 8 + k];
                    ull ha = pack2(h, h);
                    fma2(acc[i][0], ha, w.x);
                    fma2(acc[i][1], ha, w.y);
                }
            }
#pragma unroll
            for (int i = 0; i < 4; i++) {
                float l0, h0, l1, h1v;
                unpack2(acc[i][0], l0, h0);
                unpack2(acc[i][1], l1, h1v);
                float a0 = silu_f(l0), a1 = silu_f(h0);
                float a2 = silu_f(l1), a3 = silu_f(h1v);
                ulonglong2 st0, st1;
                st0.x = pack2(a0, a0); st0.y = pack2(a1, a1);
                st1.x = pack2(a2, a2); st1.y = pack2(a3, a3);
                *(ulonglong2*)&sh1d[(eb + i) * 64 + c0]     = st0;
                *(ulonglong2*)&sh1d[(eb + i) * 64 + c0 + 2] = st1;
            }
        }
        __syncthreads();

        {
            ull acc[4][2];
            ull b0 = pack2(sbr2[c0], sbr2[c0 + 1]);
            ull b1 = pack2(sbr2[c0 + 2], sbr2[c0 + 3]);
#pragma unroll
            for (int i = 0; i < 4; i++) { acc[i][0] = b0; acc[i][1] = b1; }
#pragma unroll 2
            for (int k = 0; k < 64; k += 2) {
                ulonglong2 w0 = *(const ulonglong2*)&sWr2[k * 64 + c0];
                ulonglong2 w1 = *(const ulonglong2*)&sWr2[(k + 1) * 64 + c0];
#pragma unroll
                for (int i = 0; i < 4; i++) {
                    ulonglong2 hp = *(const ulonglong2*)&sh1d[(eb + i) * 64 + k];
                    fma2(acc[i][0], hp.x, w0.x);
                    fma2(acc[i][1], hp.x, w0.y);
                    fma2(acc[i][0], hp.y, w1.x);
                    fma2(acc[i][1], hp.y, w1.y);
                }
            }
#pragma unroll
            for (int i = 0; i < 4; i++) {
                float l0, h0, l1, h1v;
                unpack2(acc[i][0], l0, h0);
                unpack2(acc[i][1], l1, h1v);
                float a0 = silu_f(l0), a1 = silu_f(h0);
                float a2 = silu_f(l1), a3 = silu_f(h1v);
                ulonglong2 st0, st1;
                st0.x = pack2(a0, a0); st0.y = pack2(a1, a1);
                st1.x = pack2(a2, a2); st1.y = pack2(a3, a3);
                *(ulonglong2*)&sh2d[(eb + i) * 64 + c0]     = st0;
                *(ulonglong2*)&sh2d[(eb + i) * 64 + c0 + 2] = st1;
            }
        }
        __syncthreads();

        ull acc3[4][NT][2];
#pragma unroll
        for (int i = 0; i < 4; i++)
#pragma unroll
            for (int t = 0; t < NT; t++) { acc3[i][t][0] = 0ULL; acc3[i][t][1] = 0ULL; }

#pragma unroll 2
        for (int k = 0; k < 64; k += 2) {
            ulonglong2 hp[4];
#pragma unroll
            for (int i = 0; i < 4; i++)
                hp[i] = *(const ulonglong2*)&sh2d[(eb + i) * 64 + k];
            const float* wr0 = &sWr3[k * 256 + c0];
            const float* wr1 = wr0 + 256;
#pragma unroll
            for (int tt = 0; tt < NT; tt++) {
                int t = FULL ? tt : tt * 2;
                ulonglong2 wa = *(const ulonglong2*)(wr0 + t * 64);
                ulonglong2 wb = *(const ulonglong2*)(wr1 + t * 64);
#pragma unroll
                for (int i = 0; i < 4; i++) {
                    fma2(acc3[i][tt][0], hp[i].x, wa.x);
                    fma2(acc3[i][tt][1], hp[i].x, wa.y);
                    fma2(acc3[i][tt][0], hp[i].y, wb.x);
                    fma2(acc3[i][tt][1], hp[i].y, wb.y);
                }
            }
        }

        {
            int cur = -1;
            float aq[4][4];
#pragma unroll
            for (int i = 0; i < 4; i++) {
                int le = eb + i;
                int rcv = prcv[le];
                if (rcv != cur) {
                    if (cur >= 0) {
                        float* agp = &g_agg[cur * 256];
#pragma unroll
                        for (int q = 0; q < 4; q++)
                            red4(agp + (c0 + q) * 4, aq[q][0], aq[q][1], aq[q][2], aq[q][3]);
                    }
                    cur = rcv;
#pragma unroll
                    for (int q = 0; q < 4; q++)
                        aq[q][0] = aq[q][1] = aq[q][2] = aq[q][3] = 0.0f;
                }
                float msk = pmk[le] * 0.03125f;
                float y0 = py[le * 3 + 0], y1v = py[le * 3 + 1], y2 = py[le * 3 + 2];
                if (FULL) {
                    const float4* svp = (const float4*)&g_supv[psnd[le] * 256];
#pragma unroll
                    for (int p = 0; p < 2; p++) {
                        float wt[4][2];
#pragma unroll
                        for (int t = 0; t < NT; t++) unpack2(acc3[i][t][p], wt[t][0], wt[t][1]);
#pragma unroll
                        for (int jj = 0; jj < 2; jj++) {
                            int q = 2 * p + jj;
                            float w0 = wt[0][jj] * msk, w1 = wt[1][jj] * msk;
                            float w2 = wt[2][jj] * msk, w3 = wt[3][jj] * msk;
                            float4 s4 = svp[c0 + q];
                            float dot = (s4.y * y0 + s4.z * y1v + s4.w * y2) * inv_sqrt3;
                            float a0 = w2 * s4.x;
                            aq[q][0] += w0 * s4.x + w1 * dot;
                            aq[q][1] += a0 * y0  + w3 * s4.y;
                            aq[q][2] += a0 * y1v + w3 * s4.z;
                            aq[q][3] += a0 * y2  + w3 * s4.w;
                        }
                    }
                } else {
                    const float* s0p = &ssup0[psnd[le] * 64];  // psnd holds species here
#pragma unroll
                    for (int p = 0; p < 2; p++) {
                        float wt0[2], wt2[2];
                        unpack2(acc3[i][0][p], wt0[0], wt0[1]);
                        unpack2(acc3[i][1][p], wt2[0], wt2[1]);
#pragma unroll
                        for (int jj = 0; jj < 2; jj++) {
                            int q = 2 * p + jj;
                            float w0 = wt0[jj] * msk;
                            float w2 = wt2[jj] * msk;
                            float sx = s0p[c0 + q];
                            float a0 = w2 * sx;
                            aq[q][0] += w0 * sx;
                            aq[q][1] += a0 * y0;
                            aq[q][2] += a0 * y1v;
                            aq[q][3] += a0 * y2;
                        }
                    }
                }
            }
            if (cur >= 0) {
                float* agp = &g_agg[cur * 256];
#pragma unroll
                for (int q = 0; q < 4; q++)
                    red4(agp + (c0 + q) * 4, aq[q][0], aq[q][1], aq[q][2], aq[q][3]);
            }
        }
        pb ^= 1;
    }
}

constexpr int NODE_SMEM = 32768 * 4;

__global__ __launch_bounds__(512, 1) void k_node(const float* __restrict__ Wms,
                                                 const float* __restrict__ Wmv,
                                                 const float* __restrict__ Wscs,
                                                 const float* __restrict__ Wscv,
                                                 const float* __restrict__ Wps,
                                                 const float* __restrict__ Wpv,
                                                 const float* __restrict__ Wread,
                                                 const float* __restrict__ WupS,
                                                 const float* __restrict__ WupV,
                                                 int l, int do_up) {
    extern __shared__ float sm[];
    float* sWms = sm;
    float* sWmv = sWms + 4096;
    float* sWps = sWmv + 4096;
    float* sWpv = sWps + 4096;
    float* sWus = sWpv + 4096;
    float* sWuv = sWus + 4096;
    float* sagg = sWuv + 4096;
    float* sold = sagg + 2048;
    float* vold = sold + 512;
    float* sts  = vold + 1536;
    float* stv  = sts + 512;
    float* snew = stv + 1536;
    float* vnew = snew + 512;

    int tid = threadIdx.x;
    for (int i = tid; i < 1024; i += 512) {
        ((float4*)sWms)[i] = ((const float4*)Wms)[i];
        ((float4*)sWmv)[i] = ((const float4*)Wmv)[i];
        ((float4*)sWps)[i] = ((const float4*)Wps)[i];
        ((float4*)sWpv)[i] = ((const float4*)Wpv)[i];
    }
    if (do_up) {
        for (int i = tid; i < 1024; i += 512) {
            ((float4*)sWus)[i] = ((const float4*)WupS)[i];
            ((float4*)sWuv)[i] = ((const float4*)WupV)[i];
        }
    }
    int slot = tid >> 6, o = tid & 63;

    for (int grp = blockIdx.x; grp < NGROUP; grp += EGRID) {
        int n = grp * 8 + slot;
        __syncthreads();
        *(float4*)&sagg[slot * 256 + o * 4] = *(const float4*)&g_agg[n * 256 + o * 4];
        *(float4*)&g_agg[n * 256 + o * 4] = make_float4(0.f, 0.f, 0.f, 0.f);
        sold[slot * 64 + o] = g_s[n * 64 + o];
        vold[slot * 192 + o * 3 + 0] = g_v[n * 192 + o * 3 + 0];
        vold[slot * 192 + o * 3 + 1] = g_v[n * 192 + o * 3 + 1];
        vold[slot * 192 + o * 3 + 2] = g_v[n * 192 + o * 3 + 2];
        __syncthreads();

        int sp = g_sp[n];
        const float* Wss = Wscs + sp * 4096;
        const float* Wsv = Wscv + sp * 4096;

        float ms = 0, mv0 = 0, mv1 = 0, mv2 = 0;
        float scs = 0, scv0 = 0, scv1 = 0, scv2 = 0;
#pragma unroll 4
        for (int c = 0; c < 64; c++) {
            const float* ag = &sagg[slot * 256 + c * 4];
            ms  += ag[0] * sWms[c * 64 + o];
            float wm = sWmv[c * 64 + o];
            mv0 += ag[1] * wm; mv1 += ag[2] * wm; mv2 += ag[3] * wm;
            scs += sold[slot * 64 + c] * Wss[c * 64 + o];
            float wv = Wsv[c * 64 + o];
            scv0 += vold[slot * 192 + c * 3 + 0] * wv;
            scv1 += vold[slot * 192 + c * 3 + 1] * wv;
            scv2 += vold[slot * 192 + c * 3 + 2] * wv;
        }
        float xfo = g_xf[n * 64 + o];
        sts[slot * 64 + o] = xfo * ms;
        stv[slot * 192 + o * 3 + 0] = xfo * mv0;
        stv[slot * 192 + o * 3 + 1] = xfo * mv1;
        stv[slot * 192 + o * 3 + 2] = xfo * mv2;
        __syncthreads();

        float sn = scs, vn0 = scv0, vn1 = scv1, vn2 = scv2;
#pragma unroll 4
        for (int c = 0; c < 64; c++) {
            sn += sts[slot * 64 + c] * sWps[c * 64 + o];
            float wp = sWpv[c * 64 + o];
            vn0 += stv[slot * 192 + c * 3 + 0] * wp;
            vn1 += stv[slot * 192 + c * 3 + 1] * wp;
            vn2 += stv[slot * 192 + c * 3 + 2] * wp;
        }
        g_s[n * 64 + o] = sn;
        g_v[n * 192 + o * 3 + 0] = vn0;
        g_v[n * 192 + o * 3 + 1] = vn1;
        g_v[n * 192 + o * 3 + 2] = vn2;
        snew[slot * 64 + o] = sn;
        vnew[slot * 192 + o * 3 + 0] = vn0;
        vnew[slot * 192 + o * 3 + 1] = vn1;
        vnew[slot * 192 + o * 3 + 2] = vn2;
        __syncthreads();

        if (o < 9) {
            int ro = o / 3, m = o % 3;
            float a = 0.0f;
#pragma unroll 8
            for (int c = 0; c < 64; c++) a += vnew[slot * 192 + c * 3 + m] * Wread[ro * 64 + c];
            g_outs[l * kN * 9 + n * 9 + o] = a;
        }

        if (do_up) {
            float su = 0.0f, u0 = 0.0f, u1 = 0.0f, u2 = 0.0f;
#pragma unroll 4
            for (int c = 0; c < 64; c++) {
                su += snew[slot * 64 + c] * sWus[c * 64 + o];
                float w = sWuv[c * 64 + o];
                u0 += vnew[slot * 192 + c * 3 + 0] * w;
                u1 += vnew[slot * 192 + c * 3 + 1] * w;
                u2 += vnew[slot * 192 + c * 3 + 2] * w;
            }
            *(float4*)&g_supv[n * 256 + o * 4] = make_float4(su, u0, u1, u2);
        }
    }
}

__global__ void k_final(float* __restrict__ out) {
    __shared__ float acc[72];
    int tid = threadIdx.x;
    if (tid < 72) acc[tid] = 0.0f;
    __syncthreads();
    int n = blockIdx.x * blockDim.x + tid;
    if (n < kN) {
        int b = g_batch[n];
#pragma unroll
        for (int j = 0; j < 9; j++) {
            float x = 0.0f;
#pragma unroll
            for (int l = 0; l < kL; l++) x += silu_f(g_outs[l * kN * 9 + n * 9 + j]);
            atomicAdd(&acc[b * 9 + j], x);
        }
    }
    __syncthreads();
    if (tid < 72) atomicAdd(&out[tid], acc[tid]);
}

extern "C" void kernel_launch(void* const* d_in, const int* in_sizes, int n_in,
                              void* d_out, int out_size) {
    const float* pos  = (const float*)d_in[0];
    const float* cell = (const float*)d_in[1];
    const float* Sij  = (const float*)d_in[2];
    const float* Wemb = (const float*)d_in[3];
    const float* Wx   = (const float*)d_in[4];
    const float* Wups = (const float*)d_in[5];
    const float* Wupv = (const float*)d_in[6];
    const float* Wr1  = (const float*)d_in[7];
    const float* br1  = (const float*)d_in[8];
    const float* Wr2  = (const float*)d_in[9];
    const float* br2  = (const float*)d_in[10];
    const float* Wr3  = (const float*)d_in[11];
    const float* Wms  = (const float*)d_in[12];
    const float* Wmv  = (const float*)d_in[13];
    const float* Wscs = (const float*)d_in[14];
    const float* Wscv = (const float*)d_in[15];
    const float* Wps  = (const float*)d_in[16];
    const float* Wpv  = (const float*)d_in[17];
    const float* Wread= (const float*)d_in[18];
    const int* ei     = (const int*)d_in[19];
    const int* braw   = (const int*)d_in[20];
    const int* spraw  = (const int*)d_in[21];
    float* out = (float*)d_out;

    cudaFuncSetAttribute(k_edge<true>,  cudaFuncAttributeMaxDynamicSharedMemorySize, EDGE_SMEM);
    cudaFuncSetAttribute(k_edge<false>, cudaFuncAttributeMaxDynamicSharedMemorySize, EDGE_SMEM);
    cudaFuncSetAttribute(k_node, cudaFuncAttributeMaxDynamicSharedMemorySize, NODE_SMEM);

    k_conv<<<(kE + 255) / 256, 256>>>(ei, braw, spraw);
    k_scan<<<1, 1024>>>(out, Wemb, Wx, Wups);
    k_geominit<<<(kN * kC + 255) / 256, 256>>>(pos, cell, Sij, Wemb);

    for (int l = 0; l < kL; l++) {
        if (l == 0)
            k_edge<false><<<EGRID, 512, EDGE_SMEM>>>(Wr1 + l * 512, br1 + l * 64,
                                                     Wr2 + l * 4096, br2 + l * 64,
                                                     Wr3 + l * 16384);
        else
            k_edge<true><<<EGRID, 512, EDGE_SMEM>>>(Wr1 + l * 512, br1 + l * 64,
                                                    Wr2 + l * 4096, br2 + l * 64,
                                                    Wr3 + l * 16384);
        int do_up = (l < kL - 1) ? 1 : 0;
        k_node<<<EGRID, 512, NODE_SMEM>>>(Wms + l * 4096, Wmv + l * 4096,
                                          Wscs + l * 32768, Wscv + l * 32768,
                                          Wps + l * 4096, Wpv + l * 4096,
                                          Wread + l * 192,
                                          Wups + (l + 1) * 4096, Wupv + (l + 1) * 4096,
                                          l, do_up);
    }
    k_final<<<(kN + 255) / 256, 256>>>(out);
}

// round 16
// speedup vs baseline: 1.0659x; 1.0184x over previous
#include <cuda_runtime.h>
#include <math.h>

constexpr int kN  = 20000;
constexpr int kG  = 8;
constexpr int kE  = 640000;
constexpr int kC  = 64;
constexpr int kNB = 8;
constexpr int kL  = 3;
constexpr int TE  = 128;
constexpr int NTILE = kE / TE;
constexpr int EGRID = 152;
constexpr int NGROUP = kN / 8;

__device__ float g_ef[kE * kNB];
__device__ float g_y1[kE * 3];
__device__ float g_mask[kE];
__device__ int   g_snd[kE];
__device__ int   g_rcv[kE];
__device__ int   g_psnd[kE];
__device__ int   g_prcv[kE];
__device__ int   g_pssp[kE];
__device__ int   g_slot[kE];
__device__ int   g_cnt[kN];
__device__ int   g_base[kN];
__device__ int   g_sp[kN];
__device__ int   g_batch[kN];
__device__ float g_s[kN * kC];
__device__ float g_xf[kN * kC];
__device__ float g_xfs[8 * kC];
__device__ float g_sup0[8 * kC];
__device__ float g_v[kN * kC * 3];
__device__ float g_supv[kN * kC * 4];
__device__ float g_agg[kN * kC * 4];
__device__ float g_outs[kL * kN * 9];

typedef unsigned long long ull;

__device__ __forceinline__ float silu_f(float x) {
    return __fdividef(x, 1.0f + __expf(-x));
}
__device__ __forceinline__ ull pack2(float lo, float hi) {
    ull r; asm("mov.b64 %0,{%1,%2};" : "=l"(r) : "f"(lo), "f"(hi)); return r;
}
__device__ __forceinline__ void unpack2(ull v, float& lo, float& hi) {
    asm("mov.b64 {%0,%1},%2;" : "=f"(lo), "=f"(hi) : "l"(v));
}
__device__ __forceinline__ void fma2(ull& d, ull a, ull b) {
    asm("fma.rn.f32x2 %0,%1,%2,%0;" : "+l"(d) : "l"(a), "l"(b));
}
__device__ __forceinline__ void red4(float* p, float a, float b, float c, float d) {
    asm volatile("red.global.add.v4.f32 [%0],{%1,%2,%3,%4};"
                 :: "l"(p), "f"(a), "f"(b), "f"(c), "f"(d) : "memory");
}
__device__ __forceinline__ void cpa16(unsigned int dst, const void* src) {
    asm volatile("cp.async.ca.shared.global [%0], [%1], 16;" :: "r"(dst), "l"(src));
}
__device__ __forceinline__ void cpa_commit() {
    asm volatile("cp.async.commit_group;" ::: "memory");
}
__device__ __forceinline__ void cpa_wait0() {
    asm volatile("cp.async.wait_group 0;" ::: "memory");
}

__global__ void k_conv(const int* eraw, const int* braw, const int* spraw) {
    __shared__ int sf;
    if (threadIdx.x == 0) {
        int f = 1;
        for (int k = 0; k < 64; k++)
            if (spraw[2 * k + 1] != 0) { f = 0; break; }
        sf = f;
    }
    __syncthreads();
    int f = sf;
    int i = blockIdx.x * blockDim.x + threadIdx.x;
    if (i < kN) {
        g_batch[i] = f ? braw[2 * i] : braw[i];
        g_sp[i]    = f ? spraw[2 * i] : spraw[i];
    }
    if (i < kE) {
        int snd = f ? eraw[2 * i]        : eraw[i];
        int rcv = f ? eraw[2 * (kE + i)] : eraw[kE + i];
        g_snd[i] = snd;
        g_rcv[i] = rcv;
        g_slot[i] = atomicAdd(&g_cnt[rcv], 1);
    }
}

__global__ void k_scan(float* __restrict__ out,
                       const float* __restrict__ Wemb,
                       const float* __restrict__ Wx,
                       const float* __restrict__ Wups0) {
    __shared__ int wsum[32];
    __shared__ int carry_s;
    int tid = threadIdx.x;
    if (tid < 72) out[tid] = 0.0f;
    if (tid < 512) {
        int sp = tid >> 6, c = tid & 63;
        float a = 0.0f, b = 0.0f;
#pragma unroll 8
        for (int k = 0; k < kC; k++) {
            float w = Wemb[sp * kC + k];
            a += w * Wx[k * kC + c];
            b += w * Wups0[k * kC + c];
        }
        g_xfs[tid]  = a;
        g_sup0[tid] = b;
    }
    if (tid == 0) carry_s = 0;
    __syncthreads();

    int lane = tid & 31, wid = tid >> 5;
    for (int base = 0; base < kN; base += 1024) {
        int i = base + tid;
        int v = (i < kN) ? g_cnt[i] : 0;
        if (i < kN) g_cnt[i] = 0;
        int x = v;
#pragma unroll
        for (int off = 1; off < 32; off <<= 1) {
            int t = __shfl_up_sync(0xffffffffu, x, off);
            if (lane >= off) x += t;
        }
        if (lane == 31) wsum[wid] = x;
        __syncthreads();
        if (wid == 0) {
            int y = wsum[lane];
#pragma unroll
            for (int off = 1; off < 32; off <<= 1) {
                int t = __shfl_up_sync(0xffffffffu, y, off);
                if (lane >= off) y += t;
            }
            wsum[lane] = y;
        }
        __syncthreads();
        int excl = x - v + (wid ? wsum[wid - 1] : 0);
        if (i < kN) g_base[i] = carry_s + excl;
        int total = wsum[31];
        __syncthreads();
        if (tid == 0) carry_s += total;
        __syncthreads();
    }
}

__global__ void k_geominit(const float* __restrict__ pos,
                           const float* __restrict__ cell,
                           const float* __restrict__ Sij,
                           const float* __restrict__ Wemb) {
    int t = blockIdx.x * blockDim.x + threadIdx.x;
    if (t < kE) {
        int e = t;
        int snd = g_snd[e], rcv = g_rcv[e];
        int p = g_base[rcv] + g_slot[e];
        g_psnd[p] = snd;
        g_prcv[p] = rcv;
        g_pssp[p] = g_sp[snd];
        int b = g_batch[snd];
        float s0 = Sij[e * 3 + 0], s1 = Sij[e * 3 + 1], s2 = Sij[e * 3 + 2];
        const float* cb = cell + b * 9;
        float sh0 = s0 * cb[0] + s1 * cb[3] + s2 * cb[6];
        float sh1 = s0 * cb[1] + s1 * cb[4] + s2 * cb[7];
        float sh2 = s0 * cb[2] + s1 * cb[5] + s2 * cb[8];
        const float invcut = 1.0f / 6.0f;
        float r0 = (pos[rcv * 3 + 0] - pos[snd * 3 + 0] + sh0) * invcut;
        float r1 = (pos[rcv * 3 + 1] - pos[snd * 3 + 1] + sh1) * invcut;
        float r2 = (pos[rcv * 3 + 2] - pos[snd * 3 + 2] + sh2) * invcut;
        float len = sqrtf(r0 * r0 + r1 * r1 + r2 * r2);
        float mask = (len > 0.0f) ? 1.0f : 0.0f;
        float safe = (len > 0.0f) ? len : 1.0f;
        float inv = 1.0f / safe;
        const float sq3 = 1.7320508075688772f;
        g_y1[p * 3 + 0] = sq3 * r0 * inv;
        g_y1[p * 3 + 1] = sq3 * r1 * inv;
        g_y1[p * 3 + 2] = sq3 * r2 * inv;
        float x = safe;
        float env = (x < 1.0f) ? (1.0f - 6.0f * x * x + 8.0f * x * x * x - 3.0f * x * x * x * x) : 0.0f;
        float fac = 1.4142135623730951f * inv * env * mask;
        const float pi = 3.14159265358979323846f;
#pragma unroll
        for (int nb = 1; nb <= kNB; nb++)
            g_ef[p * kNB + nb - 1] = fac * sinf(pi * (float)nb * safe);
        g_mask[p] = mask;
    }
    if (t < kN * kC) {
        int n = t / kC, c = t % kC;
        int sp = g_sp[n];
        g_s[t]  = Wemb[sp * kC + c];
        g_xf[t] = g_xfs[sp * kC + c];
        g_v[n * 192 + c * 3 + 0] = 0.0f;
        g_v[n * 192 + c * 3 + 1] = 0.0f;
        g_v[n * 192 + c * 3 + 2] = 0.0f;
        *(float4*)&g_agg[t * 4] = make_float4(0.f, 0.f, 0.f, 0.f);
        *(float4*)&g_supv[t * 4] = make_float4(g_sup0[sp * kC + c], 0.f, 0.f, 0.f);
    }
}

constexpr int PF_STRIDE = 1792;
constexpr int EDGE_SMEM = (512 + 64 + 64 + 4096 + 16384 + 16384 + 16384 +
                           2 * PF_STRIDE + 512) * 4;

template <bool FULL>
__global__ __launch_bounds__(512, 1) void k_edge(const float* __restrict__ Wr1,
                                                 const float* __restrict__ br1,
                                                 const float* __restrict__ Wr2,
                                                 const float* __restrict__ br2,
                                                 const float* __restrict__ Wr3) {
    extern __shared__ float sm[];
    float* sWr1 = sm;
    float* sbr1 = sWr1 + 512;
    float* sbr2 = sbr1 + 64;
    float* sWr2 = sbr2 + 64;
    float* sWr3 = sWr2 + 4096;
    ull*   sh1d = (ull*)(sWr3 + 16384);
    ull*   sh2d = sh1d + TE * 64;
    float* pf   = (float*)(sh2d + TE * 64);
    float* ssup0 = pf + 2 * PF_STRIDE;

    int tid = threadIdx.x;
    for (int i = tid; i < 128; i += 512) ((float4*)sWr1)[i] = ((const float4*)Wr1)[i];
    if (tid < 64) { sbr1[tid] = br1[tid]; sbr2[tid] = br2[tid]; }
    for (int i = tid; i < 1024; i += 512) ((float4*)sWr2)[i] = ((const float4*)Wr2)[i];
    for (int i = tid; i < 4096; i += 512) ((float4*)sWr3)[i] = ((const float4*)Wr3)[i];
    if (!FULL && tid < 512) ssup0[tid] = g_sup0[tid];

    int eg = tid >> 4;
    int cq = tid & 15;
    int c0 = cq * 4;
    int eb = eg * 4;

    const float inv_sqrt3 = 0.5773502691896258f;
    constexpr int NT = FULL ? 4 : 2;

    unsigned int pf_s0 = (unsigned int)__cvta_generic_to_shared(pf);
    auto prefetch = [&](int tile, int buf) {
        if (tid < 448) {
            unsigned int dst = pf_s0 + (buf * PF_STRIDE) * 4;
            if (tid < 256) {
                cpa16(dst + tid * 16, g_ef + tile * (TE * 8) + tid * 4);
            } else if (tid < 352) {
                int j = tid - 256;
                cpa16(dst + 1024 * 4 + j * 16, g_y1 + tile * (TE * 3) + j * 4);
            } else if (tid < 384) {
                int j = tid - 352;
                cpa16(dst + 1408 * 4 + j * 16, g_mask + tile * TE + j * 4);
            } else if (tid < 416) {
                int j = tid - 384;
                const int* src = FULL ? g_psnd : g_pssp;
                cpa16(dst + 1536 * 4 + j * 16, src + tile * TE + j * 4);
            } else {
                int j = tid - 416;
                cpa16(dst + 1664 * 4 + j * 16, g_prcv + tile * TE + j * 4);
            }
        }
        cpa_commit();
    };

    int pb = 0;
    prefetch(blockIdx.x, 0);

    for (int tile = blockIdx.x; tile < NTILE; tile += EGRID) {
        cpa_wait0();
        __syncthreads();
        float* pef = pf + pb * PF_STRIDE;
        float* py  = pef + 1024;
        float* pmk = pef + 1408;
        int*  psnd = (int*)(pef + 1536);
        int*  prcv = (int*)(pef + 1664);

        int nt = tile + EGRID;
        if (nt < NTILE) prefetch(nt, pb ^ 1);

        {
            ull acc[4][2];
            ull b0 = pack2(sbr1[c0], sbr1[c0 + 1]);
            ull b1 = pack2(sbr1[c0 + 2], sbr1[c0 + 3]);
#pragma unroll
            for (int i = 0; i < 4; i++) { acc[i][0] = b0; acc[i][1] = b1; }
#pragma unroll
            for (int k = 0; k < 8; k++) {
                ulonglong2 w = *(const ulonglong2*)&sWr1[k * 64 + c0];
#pragma unroll
                for (int i = 0; i < 4; i++) {
                    float h = pef[(eb + i) * 8 + k];
                    ull ha = pack2(h, h);
                    fma2(acc[i][0], ha, w.x);
                    fma2(acc[i][1], ha, w.y);
                }
            }
#pragma unroll
            for (int i = 0; i < 4; i++) {
                float l0, h0, l1, h1v;
                unpack2(acc[i][0], l0, h0);
                unpack2(acc[i][1], l1, h1v);
                float a0 = silu_f(l0), a1 = silu_f(h0);
                float a2 = silu_f(l1), a3 = silu_f(h1v);
                ulonglong2 st0, st1;
                st0.x = pack2(a0, a0); st0.y = pack2(a1, a1);
                st1.x = pack2(a2, a2); st1.y = pack2(a3, a3);
                *(ulonglong2*)&sh1d[(eb + i) * 64 + c0]     = st0;
                *(ulonglong2*)&sh1d[(eb + i) * 64 + c0 + 2] = st1;
            }
        }
        __syncthreads();

        {
            ull acc[4][2];
            ull b0 = pack2(sbr2[c0], sbr2[c0 + 1]);
            ull b1 = pack2(sbr2[c0 + 2], sbr2[c0 + 3]);
#pragma unroll
            for (int i = 0; i < 4; i++) { acc[i][0] = b0; acc[i][1] = b1; }
#pragma unroll 2
            for (int k = 0; k < 64; k += 2) {
                ulonglong2 w0 = *(const ulonglong2*)&sWr2[k * 64 + c0];
                ulonglong2 w1 = *(const ulonglong2*)&sWr2[(k + 1) * 64 + c0];
#pragma unroll
                for (int i = 0; i < 4; i++) {
                    ulonglong2 hp = *(const ulonglong2*)&sh1d[(eb + i) * 64 + k];
                    fma2(acc[i][0], hp.x, w0.x);
                    fma2(acc[i][1], hp.x, w0.y);
                    fma2(acc[i][0], hp.y, w1.x);
                    fma2(acc[i][1], hp.y, w1.y);
                }
            }
#pragma unroll
            for (int i = 0; i < 4; i++) {
                float l0, h0, l1, h1v;
                unpack2(acc[i][0], l0, h0);
                unpack2(acc[i][1], l1, h1v);
                float a0 = silu_f(l0), a1 = silu_f(h0);
                float a2 = silu_f(l1), a3 = silu_f(h1v);
                ulonglong2 st0, st1;
                st0.x = pack2(a0, a0); st0.y = pack2(a1, a1);
                st1.x = pack2(a2, a2); st1.y = pack2(a3, a3);
                *(ulonglong2*)&sh2d[(eb + i) * 64 + c0]     = st0;
                *(ulonglong2*)&sh2d[(eb + i) * 64 + c0 + 2] = st1;
            }
        }
        __syncthreads();

        ull acc3[4][NT][2];
#pragma unroll
        for (int i = 0; i < 4; i++)
#pragma unroll
            for (int t = 0; t < NT; t++) { acc3[i][t][0] = 0ULL; acc3[i][t][1] = 0ULL; }

#pragma unroll 2
        for (int k = 0; k < 64; k += 2) {
            ulonglong2 hp[4];
#pragma unroll
            for (int i = 0; i < 4; i++)
                hp[i] = *(const ulonglong2*)&sh2d[(eb + i) * 64 + k];
            const float* wr0 = &sWr3[k * 256 + c0];
            const float* wr1 = wr0 + 256;
#pragma unroll
            for (int tt = 0; tt < NT; tt++) {
                int t = FULL ? tt : tt * 2;
                ulonglong2 wa = *(const ulonglong2*)(wr0 + t * 64);
                ulonglong2 wb = *(const ulonglong2*)(wr1 + t * 64);
#pragma unroll
                for (int i = 0; i < 4; i++) {
                    fma2(acc3[i][tt][0], hp[i].x, wa.x);
                    fma2(acc3[i][tt][1], hp[i].x, wa.y);
                    fma2(acc3[i][tt][0], hp[i].y, wb.x);
                    fma2(acc3[i][tt][1], hp[i].y, wb.y);
                }
            }
        }

        {
            int cur = -1;
            float aq[4][4];
#pragma unroll
            for (int i = 0; i < 4; i++) {
                int le = eb + i;
                int rcv = prcv[le];
                if (rcv != cur) {
                    if (cur >= 0) {
                        float* agp = &g_agg[cur * 256];
#pragma unroll
                        for (int q = 0; q < 4; q++)
                            red4(agp + (c0 + q) * 4, aq[q][0], aq[q][1], aq[q][2], aq[q][3]);
                    }
                    cur = rcv;
#pragma unroll
                    for (int q = 0; q < 4; q++)
                        aq[q][0] = aq[q][1] = aq[q][2] = aq[q][3] = 0.0f;
                }
                float msk = pmk[le] * 0.03125f;
                float y0 = py[le * 3 + 0], y1v = py[le * 3 + 1], y2 = py[le * 3 + 2];
                if (FULL) {
                    const float4* svp = (const float4*)&g_supv[psnd[le] * 256];
                    float4 sv4[4];
#pragma unroll
                    for (int q = 0; q < 4; q++) sv4[q] = svp[c0 + q];
#pragma unroll
                    for (int p = 0; p < 2; p++) {
                        float wt[4][2];
#pragma unroll
                        for (int t = 0; t < NT; t++) unpack2(acc3[i][t][p], wt[t][0], wt[t][1]);
#pragma unroll
                        for (int jj = 0; jj < 2; jj++) {
                            int q = 2 * p + jj;
                            float w0 = wt[0][jj] * msk, w1 = wt[1][jj] * msk;
                            float w2 = wt[2][jj] * msk, w3 = wt[3][jj] * msk;
                            float4 s4 = sv4[q];
                            float dot = (s4.y * y0 + s4.z * y1v + s4.w * y2) * inv_sqrt3;
                            float a0 = w2 * s4.x;
                            aq[q][0] += w0 * s4.x + w1 * dot;
                            aq[q][1] += a0 * y0  + w3 * s4.y;
                            aq[q][2] += a0 * y1v + w3 * s4.z;
                            aq[q][3] += a0 * y2  + w3 * s4.w;
                        }
                    }
                } else {
                    const float* s0p = &ssup0[psnd[le] * 64];
#pragma unroll
                    for (int p = 0; p < 2; p++) {
                        float wt0[2], wt2[2];
                        unpack2(acc3[i][0][p], wt0[0], wt0[1]);
                        unpack2(acc3[i][1][p], wt2[0], wt2[1]);
#pragma unroll
                        for (int jj = 0; jj < 2; jj++) {
                            int q = 2 * p + jj;
                            float w0 = wt0[jj] * msk;
                            float w2 = wt2[jj] * msk;
                            float sx = s0p[c0 + q];
                            float a0 = w2 * sx;
                            aq[q][0] += w0 * sx;
                            aq[q][1] += a0 * y0;
                            aq[q][2] += a0 * y1v;
                            aq[q][3] += a0 * y2;
                        }
                    }
                }
            }
            if (cur >= 0) {
                float* agp = &g_agg[cur * 256];
#pragma unroll
                for (int q = 0; q < 4; q++)
                    red4(agp + (c0 + q) * 4, aq[q][0], aq[q][1], aq[q][2], aq[q][3]);
            }
        }
        pb ^= 1;
    }
}

constexpr int NODE_SMEM = (32768 + 128) * 4;

__global__ __launch_bounds__(512, 1) void k_node(const float* __restrict__ Wms,
                                                 const float* __restrict__ Wmv,
                                                 const float* __restrict__ Wscs,
                                                 const float* __restrict__ Wscv,
                                                 const float* __restrict__ Wps,
                                                 const float* __restrict__ Wpv,
                                                 const float* __restrict__ Wread,
                                                 const float* __restrict__ WupS,
                                                 const float* __restrict__ WupV,
                                                 int l, int do_up, int is_last,
                                                 float* __restrict__ out) {
    extern __shared__ float sm[];
    float* sWms = sm;
    float* sWmv = sWms + 4096;
    float* sWps = sWmv + 4096;
    float* sWpv = sWps + 4096;
    float* sWus = sWpv + 4096;
    float* sWuv = sWus + 4096;
    float* sagg = sWuv + 4096;
    float* sold = sagg + 2048;
    float* vold = sold + 512;
    float* sts  = vold + 1536;
    float* stv  = sts + 512;
    float* snew = stv + 1536;
    float* vnew = snew + 512;
    float* sacc = vnew + 1536;   // 72+ graph accumulators

    int tid = threadIdx.x;
    for (int i = tid; i < 1024; i += 512) {
        ((float4*)sWms)[i] = ((const float4*)Wms)[i];
        ((float4*)sWmv)[i] = ((const float4*)Wmv)[i];
        ((float4*)sWps)[i] = ((const float4*)Wps)[i];
        ((float4*)sWpv)[i] = ((const float4*)Wpv)[i];
    }
    if (do_up) {
        for (int i = tid; i < 1024; i += 512) {
            ((float4*)sWus)[i] = ((const float4*)WupS)[i];
            ((float4*)sWuv)[i] = ((const float4*)WupV)[i];
        }
    }
    if (tid < 72) sacc[tid] = 0.0f;
    int slot = tid >> 6, o = tid & 63;

    for (int grp = blockIdx.x; grp < NGROUP; grp += EGRID) {
        int n = grp * 8 + slot;
        __syncthreads();
        *(float4*)&sagg[slot * 256 + o * 4] = *(const float4*)&g_agg[n * 256 + o * 4];
        if (!is_last)
            *(float4*)&g_agg[n * 256 + o * 4] = make_float4(0.f, 0.f, 0.f, 0.f);
        sold[slot * 64 + o] = g_s[n * 64 + o];
        vold[slot * 192 + o * 3 + 0] = g_v[n * 192 + o * 3 + 0];
        vold[slot * 192 + o * 3 + 1] = g_v[n * 192 + o * 3 + 1];
        vold[slot * 192 + o * 3 + 2] = g_v[n * 192 + o * 3 + 2];
        __syncthreads();

        int sp = g_sp[n];
        const float* Wss = Wscs + sp * 4096;
        const float* Wsv = Wscv + sp * 4096;

        float ms = 0, mv0 = 0, mv1 = 0, mv2 = 0;
        float scs = 0, scv0 = 0, scv1 = 0, scv2 = 0;
#pragma unroll 4
        for (int c = 0; c < 64; c++) {
            const float* ag = &sagg[slot * 256 + c * 4];
            ms  += ag[0] * sWms[c * 64 + o];
            float wm = sWmv[c * 64 + o];
            mv0 += ag[1] * wm; mv1 += ag[2] * wm; mv2 += ag[3] * wm;
            scs += sold[slot * 64 + c] * Wss[c * 64 + o];
            float wv = Wsv[c * 64 + o];
            scv0 += vold[slot * 192 + c * 3 + 0] * wv;
            scv1 += vold[slot * 192 + c * 3 + 1] * wv;
            scv2 += vold[slot * 192 + c * 3 + 2] * wv;
        }
        float xfo = g_xf[n * 64 + o];
        sts[slot * 64 + o] = xfo * ms;
        stv[slot * 192 + o * 3 + 0] = xfo * mv0;
        stv[slot * 192 + o * 3 + 1] = xfo * mv1;
        stv[slot * 192 + o * 3 + 2] = xfo * mv2;
        __syncthreads();

        float sn = scs, vn0 = scv0, vn1 = scv1, vn2 = scv2;
#pragma unroll 4
        for (int c = 0; c < 64; c++) {
            sn += sts[slot * 64 + c] * sWps[c * 64 + o];
            float wp = sWpv[c * 64 + o];
            vn0 += stv[slot * 192 + c * 3 + 0] * wp;
            vn1 += stv[slot * 192 + c * 3 + 1] * wp;
            vn2 += stv[slot * 192 + c * 3 + 2] * wp;
        }
        if (!is_last) {
            g_s[n * 64 + o] = sn;
            g_v[n * 192 + o * 3 + 0] = vn0;
            g_v[n * 192 + o * 3 + 1] = vn1;
            g_v[n * 192 + o * 3 + 2] = vn2;
        }
        snew[slot * 64 + o] = sn;
        vnew[slot * 192 + o * 3 + 0] = vn0;
        vnew[slot * 192 + o * 3 + 1] = vn1;
        vnew[slot * 192 + o * 3 + 2] = vn2;
        __syncthreads();

        if (o < 9) {
            int ro = o / 3, m = o % 3;
            float a = 0.0f;
#pragma unroll 8
            for (int c = 0; c < 64; c++) a += vnew[slot * 192 + c * 3 + m] * Wread[ro * 64 + c];
            if (!is_last) {
                g_outs[l * kN * 9 + n * 9 + o] = a;
            } else {
                float x = silu_f(g_outs[0 * kN * 9 + n * 9 + o]) +
                          silu_f(g_outs[1 * kN * 9 + n * 9 + o]) +
                          silu_f(a);
                atomicAdd(&sacc[g_batch[n] * 9 + o], x);
            }
        }

        if (do_up) {
            float su = 0.0f, u0 = 0.0f, u1 = 0.0f, u2 = 0.0f;
#pragma unroll 4
            for (int c = 0; c < 64; c++) {
                su += snew[slot * 64 + c] * sWus[c * 64 + o];
                float w = sWuv[c * 64 + o];
                u0 += vnew[slot * 192 + c * 3 + 0] * w;
                u1 += vnew[slot * 192 + c * 3 + 1] * w;
                u2 += vnew[slot * 192 + c * 3 + 2] * w;
            }
            *(float4*)&g_supv[n * 256 + o * 4] = make_float4(su, u0, u1, u2);
        }
    }
    if (is_last) {
        __syncthreads();
        if (tid < 72) atomicAdd(&out[tid], sacc[tid]);
    }
}

extern "C" void kernel_launch(void* const* d_in, const int* in_sizes, int n_in,
                              void* d_out, int out_size) {
    const float* pos  = (const float*)d_in[0];
    const float* cell = (const float*)d_in[1];
    const float* Sij  = (const float*)d_in[2];
    const float* Wemb = (const float*)d_in[3];
    const float* Wx   = (const float*)d_in[4];
    const float* Wups = (const float*)d_in[5];
    const float* Wupv = (const float*)d_in[6];
    const float* Wr1  = (const float*)d_in[7];
    const float* br1  = (const float*)d_in[8];
    const float* Wr2  = (const float*)d_in[9];
    const float* br2  = (const float*)d_in[10];
    const float* Wr3  = (const float*)d_in[11];
    const float* Wms  = (const float*)d_in[12];
    const float* Wmv  = (const float*)d_in[13];
    const float* Wscs = (const float*)d_in[14];
    const float* Wscv = (const float*)d_in[15];
    const float* Wps  = (const float*)d_in[16];
    const float* Wpv  = (const float*)d_in[17];
    const float* Wread= (const float*)d_in[18];
    const int* ei     = (const int*)d_in[19];
    const int* braw   = (const int*)d_in[20];
    const int* spraw  = (const int*)d_in[21];
    float* out = (float*)d_out;

    cudaFuncSetAttribute(k_edge<true>,  cudaFuncAttributeMaxDynamicSharedMemorySize, EDGE_SMEM);
    cudaFuncSetAttribute(k_edge<false>, cudaFuncAttributeMaxDynamicSharedMemorySize, EDGE_SMEM);
    cudaFuncSetAttribute(k_node, cudaFuncAttributeMaxDynamicSharedMemorySize, NODE_SMEM);

    k_conv<<<(kE + 255) / 256, 256>>>(ei, braw, spraw);
    k_scan<<<1, 1024>>>(out, Wemb, Wx, Wups);
    k_geominit<<<(kN * kC + 255) / 256, 256>>>(pos, cell, Sij, Wemb);

    for (int l = 0; l < kL; l++) {
        if (l == 0)
            k_edge<false><<<EGRID, 512, EDGE_SMEM>>>(Wr1 + l * 512, br1 + l * 64,
                                                     Wr2 + l * 4096, br2 + l * 64,
                                                     Wr3 + l * 16384);
        else
            k_edge<true><<<EGRID, 512, EDGE_SMEM>>>(Wr1 + l * 512, br1 + l * 64,
                                                    Wr2 + l * 4096, br2 + l * 64,
                                                    Wr3 + l * 16384);
        int do_up = (l < kL - 1) ? 1 : 0;
        int is_last = (l == kL - 1) ? 1 : 0;
        k_node<<<EGRID, 512, NODE_SMEM>>>(Wms + l * 4096, Wmv + l * 4096,
                                          Wscs + l * 32768, Wscv + l * 32768,
                                          Wps + l * 4096, Wpv + l * 4096,
                                          Wread + l * 192,
                                          Wups + (l + 1) * 4096, Wupv + (l + 1) * 4096,
                                          l, do_up, is_last, out);
    }
}

// round 17
// speedup vs baseline: 1.0742x; 1.0078x over previous
#include <cuda_runtime.h>
#include <math.h>

constexpr int kN  = 20000;
constexpr int kG  = 8;
constexpr int kE  = 640000;
constexpr int kC  = 64;
constexpr int kNB = 8;
constexpr int kL  = 3;
constexpr int TE  = 128;
constexpr int NTILE = kE / TE;
constexpr int EGRID = 152;
constexpr int kNP = 20064;             // species-sorted padded node space
constexpr int NGP = kNP / 8;           // 2508 groups
constexpr int GPB = (NGP + EGRID - 1) / EGRID;  // 17

__device__ float g_ef[kE * kNB];
__device__ float g_y1[kE * 3];
__device__ float g_mask[kE];
__device__ int   g_snd[kE];
__device__ int   g_rcv[kE];
__device__ int   g_psnd[kE];           // permuted sender id
__device__ int   g_prcv[kE];           // permuted receiver id
__device__ int   g_pssp[kE];
__device__ int   g_slot[kE];
__device__ int   g_cnt[kN];
__device__ int   g_base[kN];
__device__ int   g_scnt[8];
__device__ int   g_spbase[9];
__device__ int   g_spslot[kN];
__device__ int   g_gsp[NGP];           // species per permuted group
__device__ int   g_sp[kN];
__device__ int   g_batch[kN];
__device__ int   g_pbatch[kNP];        // batch per permuted node, -1 pads
__device__ float g_s[kNP * kC];        // all node state in PERMUTED order
__device__ float g_xf[kNP * kC];
__device__ float g_xfs[8 * kC];
__device__ float g_sup0[8 * kC];
__device__ float g_v[kNP * kC * 3];
__device__ float g_supv[kNP * kC * 4];
__device__ float g_agg[kNP * kC * 4];
__device__ float g_outs[kL * kNP * 9];

typedef unsigned long long ull;

__device__ __forceinline__ float silu_f(float x) {
    return __fdividef(x, 1.0f + __expf(-x));
}
__device__ __forceinline__ ull pack2(float lo, float hi) {
    ull r; asm("mov.b64 %0,{%1,%2};" : "=l"(r) : "f"(lo), "f"(hi)); return r;
}
__device__ __forceinline__ void unpack2(ull v, float& lo, float& hi) {
    asm("mov.b64 {%0,%1},%2;" : "=f"(lo), "=f"(hi) : "l"(v));
}
__device__ __forceinline__ void fma2(ull& d, ull a, ull b) {
    asm("fma.rn.f32x2 %0,%1,%2,%0;" : "+l"(d) : "l"(a), "l"(b));
}
__device__ __forceinline__ void red4(float* p, float a, float b, float c, float d) {
    asm volatile("red.global.add.v4.f32 [%0],{%1,%2,%3,%4};"
                 :: "l"(p), "f"(a), "f"(b), "f"(c), "f"(d) : "memory");
}
__device__ __forceinline__ void cpa16(unsigned int dst, const void* src) {
    asm volatile("cp.async.ca.shared.global [%0], [%1], 16;" :: "r"(dst), "l"(src));
}
__device__ __forceinline__ void cpa_commit() {
    asm volatile("cp.async.commit_group;" ::: "memory");
}
__device__ __forceinline__ void cpa_wait0() {
    asm volatile("cp.async.wait_group 0;" ::: "memory");
}

__global__ void k_conv(const int* eraw, const int* braw, const int* spraw) {
    __shared__ int sf;
    if (threadIdx.x == 0) {
        int f = 1;
        for (int k = 0; k < 64; k++)
            if (spraw[2 * k + 1] != 0) { f = 0; break; }
        sf = f;
    }
    __syncthreads();
    int f = sf;
    int i = blockIdx.x * blockDim.x + threadIdx.x;
    if (i < kN) {
        g_batch[i] = f ? braw[2 * i] : braw[i];
        int sp = f ? spraw[2 * i] : spraw[i];
        g_sp[i] = sp;
        g_spslot[i] = atomicAdd(&g_scnt[sp], 1);
    }
    if (i < kE) {
        int snd = f ? eraw[2 * i]        : eraw[i];
        int rcv = f ? eraw[2 * (kE + i)] : eraw[kE + i];
        g_snd[i] = snd;
        g_rcv[i] = rcv;
        g_slot[i] = atomicAdd(&g_cnt[rcv], 1);
    }
}

__global__ void k_scan(float* __restrict__ out,
                       const float* __restrict__ Wemb,
                       const float* __restrict__ Wx,
                       const float* __restrict__ Wups0) {
    __shared__ int wsum[32];
    __shared__ int carry_s;
    __shared__ int sb[9], scn[8];
    int tid = threadIdx.x;
    if (tid < 72) out[tid] = 0.0f;
    if (tid < 512) {
        int sp = tid >> 6, c = tid & 63;
        float a = 0.0f, b = 0.0f;
#pragma unroll 8
        for (int k = 0; k < kC; k++) {
            float w = Wemb[sp * kC + k];
            a += w * Wx[k * kC + c];
            b += w * Wups0[k * kC + c];
        }
        g_xfs[tid]  = a;
        g_sup0[tid] = b;
    }
    if (tid == 0) {
        int b = 0;
        for (int s = 0; s < 8; s++) {
            int c = g_scnt[s];
            g_scnt[s] = 0;
            scn[s] = c;
            sb[s] = b;
            g_spbase[s] = b;
            b += ((c + 7) >> 3) << 3;
        }
        sb[8] = b;
        g_spbase[8] = b;
        carry_s = 0;
    }
    __syncthreads();
    // group species table
    for (int i = tid; i < NGP; i += 1024) {
        int p = i * 8;
        int s = 0;
        while (s < 7 && p >= sb[s + 1]) s++;
        g_gsp[i] = s;
    }
    // zero pad node slots + pbatch=-1
    for (int idx = tid; idx < 8 * 8 * 64; idx += 1024) {
        int s = idx >> 9;
        int j = (idx >> 6) & 7;
        int c = idx & 63;
        int p = sb[s] + scn[s] + j;
        if (p < sb[s + 1]) {
            g_s[p * 64 + c] = 0.0f;
            g_xf[p * 64 + c] = 0.0f;
            g_v[p * 192 + c * 3 + 0] = 0.0f;
            g_v[p * 192 + c * 3 + 1] = 0.0f;
            g_v[p * 192 + c * 3 + 2] = 0.0f;
            *(float4*)&g_supv[p * 256 + c * 4] = make_float4(0.f, 0.f, 0.f, 0.f);
            *(float4*)&g_agg[p * 256 + c * 4] = make_float4(0.f, 0.f, 0.f, 0.f);
            if (c == 0) g_pbatch[p] = -1;
        }
    }
    __syncthreads();

    int lane = tid & 31, wid = tid >> 5;
    for (int base = 0; base < kN; base += 1024) {
        int i = base + tid;
        int v = (i < kN) ? g_cnt[i] : 0;
        if (i < kN) g_cnt[i] = 0;
        int x = v;
#pragma unroll
        for (int off = 1; off < 32; off <<= 1) {
            int t = __shfl_up_sync(0xffffffffu, x, off);
            if (lane >= off) x += t;
        }
        if (lane == 31) wsum[wid] = x;
        __syncthreads();
        if (wid == 0) {
            int y = wsum[lane];
#pragma unroll
            for (int off = 1; off < 32; off <<= 1) {
                int t = __shfl_up_sync(0xffffffffu, y, off);
                if (lane >= off) y += t;
            }
            wsum[lane] = y;
        }
        __syncthreads();
        int excl = x - v + (wid ? wsum[wid - 1] : 0);
        if (i < kN) g_base[i] = carry_s + excl;
        int total = wsum[31];
        __syncthreads();
        if (tid == 0) carry_s += total;
        __syncthreads();
    }
}

__global__ void k_geominit(const float* __restrict__ pos,
                           const float* __restrict__ cell,
                           const float* __restrict__ Sij,
                           const float* __restrict__ Wemb) {
    int t = blockIdx.x * blockDim.x + threadIdx.x;
    if (t < kE) {
        int e = t;
        int snd = g_snd[e], rcv = g_rcv[e];
        int p = g_base[rcv] + g_slot[e];
        int ssp = g_sp[snd];
        g_psnd[p] = g_spbase[ssp] + g_spslot[snd];
        g_prcv[p] = g_spbase[g_sp[rcv]] + g_spslot[rcv];
        g_pssp[p] = ssp;
        int b = g_batch[snd];
        float s0 = Sij[e * 3 + 0], s1 = Sij[e * 3 + 1], s2 = Sij[e * 3 + 2];
        const float* cb = cell + b * 9;
        float sh0 = s0 * cb[0] + s1 * cb[3] + s2 * cb[6];
        float sh1 = s0 * cb[1] + s1 * cb[4] + s2 * cb[7];
        float sh2 = s0 * cb[2] + s1 * cb[5] + s2 * cb[8];
        const float invcut = 1.0f / 6.0f;
        float r0 = (pos[rcv * 3 + 0] - pos[snd * 3 + 0] + sh0) * invcut;
        float r1 = (pos[rcv * 3 + 1] - pos[snd * 3 + 1] + sh1) * invcut;
        float r2 = (pos[rcv * 3 + 2] - pos[snd * 3 + 2] + sh2) * invcut;
        float len = sqrtf(r0 * r0 + r1 * r1 + r2 * r2);
        float mask = (len > 0.0f) ? 1.0f : 0.0f;
        float safe = (len > 0.0f) ? len : 1.0f;
        float inv = 1.0f / safe;
        const float sq3 = 1.7320508075688772f;
        g_y1[p * 3 + 0] = sq3 * r0 * inv;
        g_y1[p * 3 + 1] = sq3 * r1 * inv;
        g_y1[p * 3 + 2] = sq3 * r2 * inv;
        float x = safe;
        float env = (x < 1.0f) ? (1.0f - 6.0f * x * x + 8.0f * x * x * x - 3.0f * x * x * x * x) : 0.0f;
        float fac = 1.4142135623730951f * inv * env * mask;
        const float pi = 3.14159265358979323846f;
#pragma unroll
        for (int nb = 1; nb <= kNB; nb++)
            g_ef[p * kNB + nb - 1] = fac * sinf(pi * (float)nb * safe);
        g_mask[p] = mask;
    }
    if (t < kN * kC) {
        int n = t / kC, c = t % kC;
        int sp = g_sp[n];
        int pn = g_spbase[sp] + g_spslot[n];
        g_s[pn * 64 + c]  = Wemb[sp * kC + c];
        g_xf[pn * 64 + c] = g_xfs[sp * kC + c];
        g_v[pn * 192 + c * 3 + 0] = 0.0f;
        g_v[pn * 192 + c * 3 + 1] = 0.0f;
        g_v[pn * 192 + c * 3 + 2] = 0.0f;
        *(float4*)&g_agg[pn * 256 + c * 4] = make_float4(0.f, 0.f, 0.f, 0.f);
        *(float4*)&g_supv[pn * 256 + c * 4] = make_float4(g_sup0[sp * kC + c], 0.f, 0.f, 0.f);
        if (c == 0) g_pbatch[pn] = g_batch[n];
    }
}

constexpr int PF_STRIDE = 1792;
constexpr int EDGE_SMEM = (512 + 64 + 64 + 4096 + 16384 + 16384 + 16384 +
                           2 * PF_STRIDE + 512) * 4;

template <bool FULL>
__global__ __launch_bounds__(512, 1) void k_edge(const float* __restrict__ Wr1,
                                                 const float* __restrict__ br1,
                                                 const float* __restrict__ Wr2,
                                                 const float* __restrict__ br2,
                                                 const float* __restrict__ Wr3) {
    extern __shared__ float sm[];
    float* sWr1 = sm;
    float* sbr1 = sWr1 + 512;
    float* sbr2 = sbr1 + 64;
    float* sWr2 = sbr2 + 64;
    float* sWr3 = sWr2 + 4096;
    ull*   sh1d = (ull*)(sWr3 + 16384);
    ull*   sh2d = sh1d + TE * 64;
    float* pf   = (float*)(sh2d + TE * 64);
    float* ssup0 = pf + 2 * PF_STRIDE;

    int tid = threadIdx.x;
    for (int i = tid; i < 128; i += 512) ((float4*)sWr1)[i] = ((const float4*)Wr1)[i];
    if (tid < 64) { sbr1[tid] = br1[tid]; sbr2[tid] = br2[tid]; }
    for (int i = tid; i < 1024; i += 512) ((float4*)sWr2)[i] = ((const float4*)Wr2)[i];
    for (int i = tid; i < 4096; i += 512) ((float4*)sWr3)[i] = ((const float4*)Wr3)[i];
    if (!FULL && tid < 512) ssup0[tid] = g_sup0[tid];

    int eg = tid >> 4;
    int cq = tid & 15;
    int c0 = cq * 4;
    int eb = eg * 4;

    const float inv_sqrt3 = 0.5773502691896258f;
    constexpr int NT = FULL ? 4 : 2;

    unsigned int pf_s0 = (unsigned int)__cvta_generic_to_shared(pf);
    auto prefetch = [&](int tile, int buf) {
        if (tid < 448) {
            unsigned int dst = pf_s0 + (buf * PF_STRIDE) * 4;
            if (tid < 256) {
                cpa16(dst + tid * 16, g_ef + tile * (TE * 8) + tid * 4);
            } else if (tid < 352) {
                int j = tid - 256;
                cpa16(dst + 1024 * 4 + j * 16, g_y1 + tile * (TE * 3) + j * 4);
            } else if (tid < 384) {
                int j = tid - 352;
                cpa16(dst + 1408 * 4 + j * 16, g_mask + tile * TE + j * 4);
            } else if (tid < 416) {
                int j = tid - 384;
                const int* src = FULL ? g_psnd : g_pssp;
                cpa16(dst + 1536 * 4 + j * 16, src + tile * TE + j * 4);
            } else {
                int j = tid - 416;
                cpa16(dst + 1664 * 4 + j * 16, g_prcv + tile * TE + j * 4);
            }
        }
        cpa_commit();
    };

    int pb = 0;
    prefetch(blockIdx.x, 0);

    for (int tile = blockIdx.x; tile < NTILE; tile += EGRID) {
        cpa_wait0();
        __syncthreads();
        float* pef = pf + pb * PF_STRIDE;
        float* py  = pef + 1024;
        float* pmk = pef + 1408;
        int*  psnd = (int*)(pef + 1536);
        int*  prcv = (int*)(pef + 1664);

        int nt = tile + EGRID;
        if (nt < NTILE) prefetch(nt, pb ^ 1);

        {
            ull acc[4][2];
            ull b0 = pack2(sbr1[c0], sbr1[c0 + 1]);
            ull b1 = pack2(sbr1[c0 + 2], sbr1[c0 + 3]);
#pragma unroll
            for (int i = 0; i < 4; i++) { acc[i][0] = b0; acc[i][1] = b1; }
#pragma unroll
            for (int k = 0; k < 8; k++) {
                ulonglong2 w = *(const ulonglong2*)&sWr1[k * 64 + c0];
#pragma unroll
                for (int i = 0; i < 4; i++) {
                    float h = pef[(eb + i) * 8 + k];
                    ull ha = pack2(h, h);
                    fma2(acc[i][0], ha, w.x);
                    fma2(acc[i][1], ha, w.y);
                }
            }
#pragma unroll
            for (int i = 0; i < 4; i++) {
                float l0, h0, l1, h1v;
                unpack2(acc[i][0], l0, h0);
                unpack2(acc[i][1], l1, h1v);
                float a0 = silu_f(l0), a1 = silu_f(h0);
                float a2 = silu_f(l1), a3 = silu_f(h1v);
                ulonglong2 st0, st1;
                st0.x = pack2(a0, a0); st0.y = pack2(a1, a1);
                st1.x = pack2(a2, a2); st1.y = pack2(a3, a3);
                *(ulonglong2*)&sh1d[(eb + i) * 64 + c0]     = st0;
                *(ulonglong2*)&sh1d[(eb + i) * 64 + c0 + 2] = st1;
            }
        }
        __syncthreads();

        {
            ull acc[4][2];
            ull b0 = pack2(sbr2[c0], sbr2[c0 + 1]);
            ull b1 = pack2(sbr2[c0 + 2], sbr2[c0 + 3]);
#pragma unroll
            for (int i = 0; i < 4; i++) { acc[i][0] = b0; acc[i][1] = b1; }
#pragma unroll 2
            for (int k = 0; k < 64; k += 2) {
                ulonglong2 w0 = *(const ulonglong2*)&sWr2[k * 64 + c0];
                ulonglong2 w1 = *(const ulonglong2*)&sWr2[(k + 1) * 64 + c0];
#pragma unroll
                for (int i = 0; i < 4; i++) {
                    ulonglong2 hp = *(const ulonglong2*)&sh1d[(eb + i) * 64 + k];
                    fma2(acc[i][0], hp.x, w0.x);
                    fma2(acc[i][1], hp.x, w0.y);
                    fma2(acc[i][0], hp.y, w1.x);
                    fma2(acc[i][1], hp.y, w1.y);
                }
            }
#pragma unroll
            for (int i = 0; i < 4; i++) {
                float l0, h0, l1, h1v;
                unpack2(acc[i][0], l0, h0);
                unpack2(acc[i][1], l1, h1v);
                float a0 = silu_f(l0), a1 = silu_f(h0);
                float a2 = silu_f(l1), a3 = silu_f(h1v);
                ulonglong2 st0, st1;
                st0.x = pack2(a0, a0); st0.y = pack2(a1, a1);
                st1.x = pack2(a2, a2); st1.y = pack2(a3, a3);
                *(ulonglong2*)&sh2d[(eb + i) * 64 + c0]     = st0;
                *(ulonglong2*)&sh2d[(eb + i) * 64 + c0 + 2] = st1;
            }
        }
        __syncthreads();

        ull acc3[4][NT][2];
#pragma unroll
        for (int i = 0; i < 4; i++)
#pragma unroll
            for (int t = 0; t < NT; t++) { acc3[i][t][0] = 0ULL; acc3[i][t][1] = 0ULL; }

#pragma unroll 2
        for (int k = 0; k < 64; k += 2) {
            ulonglong2 hp[4];
#pragma unroll
            for (int i = 0; i < 4; i++)
                hp[i] = *(const ulonglong2*)&sh2d[(eb + i) * 64 + k];
            const float* wr0 = &sWr3[k * 256 + c0];
            const float* wr1 = wr0 + 256;
#pragma unroll
            for (int tt = 0; tt < NT; tt++) {
                int t = FULL ? tt : tt * 2;
                ulonglong2 wa = *(const ulonglong2*)(wr0 + t * 64);
                ulonglong2 wb = *(const ulonglong2*)(wr1 + t * 64);
#pragma unroll
                for (int i = 0; i < 4; i++) {
                    fma2(acc3[i][tt][0], hp[i].x, wa.x);
                    fma2(acc3[i][tt][1], hp[i].x, wa.y);
                    fma2(acc3[i][tt][0], hp[i].y, wb.x);
                    fma2(acc3[i][tt][1], hp[i].y, wb.y);
                }
            }
        }

        {
            int cur = -1;
            float aq[4][4];
#pragma unroll
            for (int i = 0; i < 4; i++) {
                int le = eb + i;
                int rcv = prcv[le];
                if (rcv != cur) {
                    if (cur >= 0) {
                        float* agp = &g_agg[cur * 256];
#pragma unroll
                        for (int q = 0; q < 4; q++)
                            red4(agp + (c0 + q) * 4, aq[q][0], aq[q][1], aq[q][2], aq[q][3]);
                    }
                    cur = rcv;
#pragma unroll
                    for (int q = 0; q < 4; q++)
                        aq[q][0] = aq[q][1] = aq[q][2] = aq[q][3] = 0.0f;
                }
                float msk = pmk[le] * 0.03125f;
                float y0 = py[le * 3 + 0], y1v = py[le * 3 + 1], y2 = py[le * 3 + 2];
                if (FULL) {
                    const float4* svp = (const float4*)&g_supv[psnd[le] * 256];
                    float4 sv4[4];
#pragma unroll
                    for (int q = 0; q < 4; q++) sv4[q] = svp[c0 + q];
#pragma unroll
                    for (int p = 0; p < 2; p++) {
                        float wt[4][2];
#pragma unroll
                        for (int t = 0; t < NT; t++) unpack2(acc3[i][t][p], wt[t][0], wt[t][1]);
#pragma unroll
                        for (int jj = 0; jj < 2; jj++) {
                            int q = 2 * p + jj;
                            float w0 = wt[0][jj] * msk, w1 = wt[1][jj] * msk;
                            float w2 = wt[2][jj] * msk, w3 = wt[3][jj] * msk;
                            float4 s4 = sv4[q];
                            float dot = (s4.y * y0 + s4.z * y1v + s4.w * y2) * inv_sqrt3;
                            float a0 = w2 * s4.x;
                            aq[q][0] += w0 * s4.x + w1 * dot;
                            aq[q][1] += a0 * y0  + w3 * s4.y;
                            aq[q][2] += a0 * y1v + w3 * s4.z;
                            aq[q][3] += a0 * y2  + w3 * s4.w;
                        }
                    }
                } else {
                    const float* s0p = &ssup0[psnd[le] * 64];
#pragma unroll
                    for (int p = 0; p < 2; p++) {
                        float wt0[2], wt2[2];
                        unpack2(acc3[i][0][p], wt0[0], wt0[1]);
                        unpack2(acc3[i][1][p], wt2[0], wt2[1]);
#pragma unroll
                        for (int jj = 0; jj < 2; jj++) {
                            int q = 2 * p + jj;
                            float w0 = wt0[jj] * msk;
                            float w2 = wt2[jj] * msk;
                            float sx = s0p[c0 + q];
                            float a0 = w2 * sx;
                            aq[q][0] += w0 * sx;
                            aq[q][1] += a0 * y0;
                            aq[q][2] += a0 * y1v;
                            aq[q][3] += a0 * y2;
                        }
                    }
                }
            }
            if (cur >= 0) {
                float* agp = &g_agg[cur * 256];
#pragma unroll
                for (int q = 0; q < 4; q++)
                    red4(agp + (c0 + q) * 4, aq[q][0], aq[q][1], aq[q][2], aq[q][3]);
            }
        }
        pb ^= 1;
    }
}

constexpr int NODE_SMEM = (32768 + 128 + 8192) * 4;

__global__ __launch_bounds__(512, 1) void k_node(const float* __restrict__ Wms,
                                                 const float* __restrict__ Wmv,
                                                 const float* __restrict__ Wscs,
                                                 const float* __restrict__ Wscv,
                                                 const float* __restrict__ Wps,
                                                 const float* __restrict__ Wpv,
                                                 const float* __restrict__ Wread,
                                                 const float* __restrict__ WupS,
                                                 const float* __restrict__ WupV,
                                                 int l, int do_up, int is_last,
                                                 float* __restrict__ out) {
    extern __shared__ float sm[];
    float* sWms = sm;
    float* sWmv = sWms + 4096;
    float* sWps = sWmv + 4096;
    float* sWpv = sWps + 4096;
    float* sWus = sWpv + 4096;
    float* sWuv = sWus + 4096;
    float* sWss = sWuv + 4096;
    float* sWsv = sWss + 4096;
    float* sagg = sWsv + 4096;
    float* sold = sagg + 2048;
    float* vold = sold + 512;
    float* sts  = vold + 1536;
    float* stv  = sts + 512;
    float* snew = stv + 1536;
    float* vnew = snew + 512;
    float* sacc = vnew + 1536;

    int tid = threadIdx.x;
    for (int i = tid; i < 1024; i += 512) {
        ((float4*)sWms)[i] = ((const float4*)Wms)[i];
        ((float4*)sWmv)[i] = ((const float4*)Wmv)[i];
        ((float4*)sWps)[i] = ((const float4*)Wps)[i];
        ((float4*)sWpv)[i] = ((const float4*)Wpv)[i];
    }
    if (do_up) {
        for (int i = tid; i < 1024; i += 512) {
            ((float4*)sWus)[i] = ((const float4*)WupS)[i];
            ((float4*)sWuv)[i] = ((const float4*)WupV)[i];
        }
    }
    if (tid < 72) sacc[tid] = 0.0f;
    int slot = tid >> 6, o = tid & 63;

    int g0 = blockIdx.x * GPB;
    int g1 = g0 + GPB; if (g1 > NGP) g1 = NGP;
    int cur_sp = -1;

    for (int grp = g0; grp < g1; grp++) {
        int sp = g_gsp[grp];
        __syncthreads();
        if (sp != cur_sp) {
            const float* Wssg = Wscs + sp * 4096;
            const float* Wsvg = Wscv + sp * 4096;
            for (int i = tid; i < 1024; i += 512) {
                ((float4*)sWss)[i] = ((const float4*)Wssg)[i];
                ((float4*)sWsv)[i] = ((const float4*)Wsvg)[i];
            }
            cur_sp = sp;
        }
        int n = grp * 8 + slot;
        *(float4*)&sagg[slot * 256 + o * 4] = *(const float4*)&g_agg[n * 256 + o * 4];
        if (!is_last)
            *(float4*)&g_agg[n * 256 + o * 4] = make_float4(0.f, 0.f, 0.f, 0.f);
        sold[slot * 64 + o] = g_s[n * 64 + o];
        vold[slot * 192 + o * 3 + 0] = g_v[n * 192 + o * 3 + 0];
        vold[slot * 192 + o * 3 + 1] = g_v[n * 192 + o * 3 + 1];
        vold[slot * 192 + o * 3 + 2] = g_v[n * 192 + o * 3 + 2];
        __syncthreads();

        float ms = 0, mv0 = 0, mv1 = 0, mv2 = 0;
        float scs = 0, scv0 = 0, scv1 = 0, scv2 = 0;
#pragma unroll 4
        for (int c = 0; c < 64; c++) {
            const float* ag = &sagg[slot * 256 + c * 4];
            ms  += ag[0] * sWms[c * 64 + o];
            float wm = sWmv[c * 64 + o];
            mv0 += ag[1] * wm; mv1 += ag[2] * wm; mv2 += ag[3] * wm;
            scs += sold[slot * 64 + c] * sWss[c * 64 + o];
            float wv = sWsv[c * 64 + o];
            scv0 += vold[slot * 192 + c * 3 + 0] * wv;
            scv1 += vold[slot * 192 + c * 3 + 1] * wv;
            scv2 += vold[slot * 192 + c * 3 + 2] * wv;
        }
        float xfo = g_xf[n * 64 + o];
        sts[slot * 64 + o] = xfo * ms;
        stv[slot * 192 + o * 3 + 0] = xfo * mv0;
        stv[slot * 192 + o * 3 + 1] = xfo * mv1;
        stv[slot * 192 + o * 3 + 2] = xfo * mv2;
        __syncthreads();

        float sn = scs, vn0 = scv0, vn1 = scv1, vn2 = scv2;
#pragma unroll 4
        for (int c = 0; c < 64; c++) {
            sn += sts[slot * 64 + c] * sWps[c * 64 + o];
            float wp = sWpv[c * 64 + o];
            vn0 += stv[slot * 192 + c * 3 + 0] * wp;
            vn1 += stv[slot * 192 + c * 3 + 1] * wp;
            vn2 += stv[slot * 192 + c * 3 + 2] * wp;
        }
        if (!is_last) {
            g_s[n * 64 + o] = sn;
            g_v[n * 192 + o * 3 + 0] = vn0;
            g_v[n * 192 + o * 3 + 1] = vn1;
            g_v[n * 192 + o * 3 + 2] = vn2;
        }
        snew[slot * 64 + o] = sn;
        vnew[slot * 192 + o * 3 + 0] = vn0;
        vnew[slot * 192 + o * 3 + 1] = vn1;
        vnew[slot * 192 + o * 3 + 2] = vn2;
        __syncthreads();

        if (o < 9) {
            int ro = o / 3, m = o % 3;
            float a = 0.0f;
#pragma unroll 8
            for (int c = 0; c < 64; c++) a += vnew[slot * 192 + c * 3 + m] * Wread[ro * 64 + c];
            if (!is_last) {
                g_outs[l * kNP * 9 + n * 9 + o] = a;
            } else {
                int b = g_pbatch[n];
                if (b >= 0) {
                    float x = silu_f(g_outs[0 * kNP * 9 + n * 9 + o]) +
                              silu_f(g_outs[1 * kNP * 9 + n * 9 + o]) +
                              silu_f(a);
                    atomicAdd(&sacc[b * 9 + o], x);
                }
            }
        }

        if (do_up) {
            float su = 0.0f, u0 = 0.0f, u1 = 0.0f, u2 = 0.0f;
#pragma unroll 4
            for (int c = 0; c < 64; c++) {
                su += snew[slot * 64 + c] * sWus[c * 64 + o];
                float w = sWuv[c * 64 + o];
                u0 += vnew[slot * 192 + c * 3 + 0] * w;
                u1 += vnew[slot * 192 + c * 3 + 1] * w;
                u2 += vnew[slot * 192 + c * 3 + 2] * w;
            }
            *(float4*)&g_supv[n * 256 + o * 4] = make_float4(su, u0, u1, u2);
        }
    }
    if (is_last) {
        __syncthreads();
        if (tid < 72) atomicAdd(&out[tid], sacc[tid]);
    }
}

extern "C" void kernel_launch(void* const* d_in, const int* in_sizes, int n_in,
                              void* d_out, int out_size) {
    const float* pos  = (const float*)d_in[0];
    const float* cell = (const float*)d_in[1];
    const float* Sij  = (const float*)d_in[2];
    const float* Wemb = (const float*)d_in[3];
    const float* Wx   = (const float*)d_in[4];
    const float* Wups = (const float*)d_in[5];
    const float* Wupv = (const float*)d_in[6];
    const float* Wr1  = (const float*)d_in[7];
    const float* br1  = (const float*)d_in[8];
    const float* Wr2  = (const float*)d_in[9];
    const float* br2  = (const float*)d_in[10];
    const float* Wr3  = (const float*)d_in[11];
    const float* Wms  = (const float*)d_in[12];
    const float* Wmv  = (const float*)d_in[13];
    const float* Wscs = (const float*)d_in[14];
    const float* Wscv = (const float*)d_in[15];
    const float* Wps  = (const float*)d_in[16];
    const float* Wpv  = (const float*)d_in[17];
    const float* Wread= (const float*)d_in[18];
    const int* ei     = (const int*)d_in[19];
    const int* braw   = (const int*)d_in[20];
    const int* spraw  = (const int*)d_in[21];
    float* out = (float*)d_out;

    cudaFuncSetAttribute(k_edge<true>,  cudaFuncAttributeMaxDynamicSharedMemorySize, EDGE_SMEM);
    cudaFuncSetAttribute(k_edge<false>, cudaFuncAttributeMaxDynamicSharedMemorySize, EDGE_SMEM);
    cudaFuncSetAttribute(k_node, cudaFuncAttributeMaxDynamicSharedMemorySize, NODE_SMEM);

    k_conv<<<(kE + 255) / 256, 256>>>(ei, braw, spraw);
    k_scan<<<1, 1024>>>(out, Wemb, Wx, Wups);
    k_geominit<<<(kN * kC + 255) / 256, 256>>>(pos, cell, Sij, Wemb);

    for (int l = 0; l < kL; l++) {
        if (l == 0)
            k_edge<false><<<EGRID, 512, EDGE_SMEM>>>(Wr1 + l * 512, br1 + l * 64,
                                                     Wr2 + l * 4096, br2 + l * 64,
                                                     Wr3 + l * 16384);
        else
            k_edge<true><<<EGRID, 512, EDGE_SMEM>>>(Wr1 + l * 512, br1 + l * 64,
                                                    Wr2 + l * 4096, br2 + l * 64,
                                                    Wr3 + l * 16384);
        int do_up = (l < kL - 1) ? 1 : 0;
        int is_last = (l == kL - 1) ? 1 : 0;
        k_node<<<EGRID, 512, NODE_SMEM>>>(Wms + l * 4096, Wmv + l * 4096,
                                          Wscs + l * 32768, Wscv + l * 32768,
                                          Wps + l * 4096, Wpv + l * 4096,
                                          Wread + l * 192,
                                          Wups + (l + 1) * 4096, Wupv + (l + 1) * 4096,
                                          l, do_up, is_last, out);
    }
}